// round 2
// baseline (speedup 1.0000x reference)
#include <cuda_runtime.h>
#include <math.h>

#define SEQ 2048
#define HIDDEN 2048
#define INTER 4096
#define NH 64
#define DH 64
#define DS 128
#define CHUNK 256
#define NCH 8
#define CONV_DIM 4352
#define PROJ_DIM 8512

// -------- scratch (device globals; no allocation allowed) --------
__device__ float g_proj[SEQ * PROJ_DIM];            // [s][8512]
__device__ float g_conv[SEQ * CONV_DIM];            // [s][4352]  (x | B | C) after conv+silu
__device__ float g_dt[SEQ * NH];                    // softplus(dt)
__device__ float g_acum[SEQ * NH];                  // cumsum(dt*A) per chunk
__device__ float g_cb[NCH * CHUNK * CHUNK];         // [c][t][s]  C_t . B_s (shared across heads, G=1)
__device__ float g_states[NCH * NH * DH * DS];      // chunk end states [c][h][p][n]
__device__ float g_prev[NCH * NH * DH * DS];        // state at chunk start
__device__ float g_y[SEQ * INTER];                  // SSD out, then normed in-place

// ======================= GEMM (NT): C[M,N] = A[M,K] * B[N,K]^T =======================
template<int K, int N>
__device__ __forceinline__ void gemm_nt_body(const float* __restrict__ A,
                                             const float* __restrict__ B,
                                             float* __restrict__ C) {
    __shared__ float As[32][132];   // [k][m], padded
    __shared__ float Bs[32][68];    // [k][n], padded
    const int bm = blockIdx.y * 128;
    const int bn = blockIdx.x * 64;
    const int tid = threadIdx.x;
    const int tx = tid & 15;        // n dir (x4)
    const int ty = tid >> 4;        // m dir (x8)
    const int lc = tid & 31;        // k within tile for loads
    const int lr = tid >> 5;        // row base for loads

    float acc[8][4];
#pragma unroll
    for (int i = 0; i < 8; i++)
#pragma unroll
        for (int j = 0; j < 4; j++) acc[i][j] = 0.f;

    const float* Ap = A + (size_t)bm * K + lc;
    const float* Bp = B + (size_t)bn * K + lc;

    for (int k0 = 0; k0 < K; k0 += 32) {
        __syncthreads();
#pragma unroll
        for (int i = 0; i < 16; i++)
            As[lc][lr + i * 8] = Ap[(size_t)(lr + i * 8) * K + k0];
#pragma unroll
        for (int i = 0; i < 8; i++)
            Bs[lc][lr + i * 8] = Bp[(size_t)(lr + i * 8) * K + k0];
        __syncthreads();
#pragma unroll
        for (int k = 0; k < 32; k++) {
            float4 a0 = *(const float4*)&As[k][ty * 8];
            float4 a1 = *(const float4*)&As[k][ty * 8 + 4];
            float4 b0 = *(const float4*)&Bs[k][tx * 4];
            float av[8] = {a0.x, a0.y, a0.z, a0.w, a1.x, a1.y, a1.z, a1.w};
            float bv[4] = {b0.x, b0.y, b0.z, b0.w};
#pragma unroll
            for (int i = 0; i < 8; i++)
#pragma unroll
                for (int j = 0; j < 4; j++)
                    acc[i][j] = fmaf(av[i], bv[j], acc[i][j]);
        }
    }
#pragma unroll
    for (int i = 0; i < 8; i++) {
        *(float4*)&C[(size_t)(bm + ty * 8 + i) * N + bn + tx * 4] =
            make_float4(acc[i][0], acc[i][1], acc[i][2], acc[i][3]);
    }
}

__global__ __launch_bounds__(256) void gemm1_kernel(const float* __restrict__ x,
                                                    const float* __restrict__ W_in) {
    gemm_nt_body<HIDDEN, PROJ_DIM>(x, W_in, g_proj);
}
__global__ __launch_bounds__(256) void gemm2_kernel(const float* __restrict__ W_out,
                                                    float* __restrict__ out) {
    gemm_nt_body<INTER, HIDDEN>(g_y, W_out, out);
}

// ======================= depthwise causal conv (K=4) + SiLU =======================
__global__ void conv_silu_kernel(const float* __restrict__ conv_w,
                                 const float* __restrict__ conv_b) {
    int idx = blockIdx.x * blockDim.x + threadIdx.x;
    if (idx >= SEQ * CONV_DIM) return;
    int s = idx / CONV_DIM;
    int c = idx - s * CONV_DIM;
    float w0 = conv_w[c * 4 + 0], w1 = conv_w[c * 4 + 1];
    float w2 = conv_w[c * 4 + 2], w3 = conv_w[c * 4 + 3];
    const float* col = g_proj + INTER + c;
    float acc = conv_b[c];
    if (s >= 3) acc = fmaf(col[(size_t)(s - 3) * PROJ_DIM], w0, acc);
    if (s >= 2) acc = fmaf(col[(size_t)(s - 2) * PROJ_DIM], w1, acc);
    if (s >= 1) acc = fmaf(col[(size_t)(s - 1) * PROJ_DIM], w2, acc);
    acc = fmaf(col[(size_t)s * PROJ_DIM], w3, acc);
    float sig = 1.f / (1.f + __expf(-acc));
    g_conv[idx] = acc * sig;
}

// ======================= dt = softplus(dt_raw + dt_bias) =======================
__global__ void dt_kernel(const float* __restrict__ dt_bias) {
    int idx = blockIdx.x * blockDim.x + threadIdx.x;   // SEQ*NH
    int h = idx & 63;
    int s = idx >> 6;
    float v = g_proj[(size_t)s * PROJ_DIM + (INTER + CONV_DIM) + h] + dt_bias[h];
    g_dt[idx] = (v > 20.f) ? v : log1pf(__expf(v));
}

// ======================= per-chunk cumulative sum of dt*A =======================
__global__ void acum_kernel(const float* __restrict__ A_log) {
    int c = blockIdx.x;
    int h = threadIdx.x;   // 64 threads
    float A = -__expf(A_log[h]);
    float run = 0.f;
    const float* dtp = g_dt + (size_t)c * CHUNK * NH + h;
    float* acp = g_acum + (size_t)c * CHUNK * NH + h;
    for (int l = 0; l < CHUNK; l++) {
        run = fmaf(dtp[l * NH], A, run);
        acp[l * NH] = run;
    }
}

// ======================= CB[c][t][s] = C_t . B_s (shared over heads), s<=t tiles only =======================
__global__ __launch_bounds__(256) void cb_kernel() {
    int st = blockIdx.x, tt = blockIdx.y, c = blockIdx.z;
    if (st > tt) return;
    __shared__ float Cs[32][68];
    __shared__ float Bs2[32][68];
    const int tid = threadIdx.x;
    const int tx = tid & 15, ty = tid >> 4;
    float acc[4][4] = {};
    for (int n0 = 0; n0 < DS; n0 += 32) {
        __syncthreads();
        for (int e = tid; e < 64 * 32; e += 256) {
            int r = e >> 5, kk = e & 31;
            Cs[kk][r]  = g_conv[(size_t)(c * CHUNK + tt * 64 + r) * CONV_DIM + INTER + DS + n0 + kk];
            Bs2[kk][r] = g_conv[(size_t)(c * CHUNK + st * 64 + r) * CONV_DIM + INTER + n0 + kk];
        }
        __syncthreads();
#pragma unroll
        for (int k = 0; k < 32; k++) {
            float4 a = *(const float4*)&Cs[k][ty * 4];
            float4 b = *(const float4*)&Bs2[k][tx * 4];
            float av[4] = {a.x, a.y, a.z, a.w};
            float bv[4] = {b.x, b.y, b.z, b.w};
#pragma unroll
            for (int i = 0; i < 4; i++)
#pragma unroll
                for (int j = 0; j < 4; j++)
                    acc[i][j] = fmaf(av[i], bv[j], acc[i][j]);
        }
    }
#pragma unroll
    for (int i = 0; i < 4; i++)
        *(float4*)&g_cb[(size_t)c * CHUNK * CHUNK + (size_t)(tt * 64 + ty * 4 + i) * CHUNK + st * 64 + tx * 4] =
            make_float4(acc[i][0], acc[i][1], acc[i][2], acc[i][3]);
}

// ======================= chunk end states: states[c][h][p][n] =======================
__global__ __launch_bounds__(256) void states_kernel() {
    int h = blockIdx.x, c = blockIdx.y;
    __shared__ float Bt[32][DS];
    __shared__ float Xt[32][DH];
    __shared__ float wv[32];
    const int tid = threadIdx.x;
    const int p = tid >> 2, ng = tid & 3;
    float acc[32];
#pragma unroll
    for (int j = 0; j < 32; j++) acc[j] = 0.f;
    float Aend = g_acum[(size_t)(c * CHUNK + CHUNK - 1) * NH + h];
    for (int lt = 0; lt < 8; lt++) {
        __syncthreads();
        for (int e = tid; e < 32 * DS; e += 256) {
            int r = e >> 7, n = e & 127;
            Bt[r][n] = g_conv[(size_t)(c * CHUNK + lt * 32 + r) * CONV_DIM + INTER + n];
        }
        for (int e = tid; e < 32 * DH; e += 256) {
            int r = e >> 6, pp = e & 63;
            Xt[r][pp] = g_conv[(size_t)(c * CHUNK + lt * 32 + r) * CONV_DIM + h * DH + pp];
        }
        if (tid < 32) {
            int l = lt * 32 + tid;
            float ac = g_acum[(size_t)(c * CHUNK + l) * NH + h];
            wv[tid] = __expf(Aend - ac) * g_dt[(size_t)(c * CHUNK + l) * NH + h];
        }
        __syncthreads();
#pragma unroll 4
        for (int ls = 0; ls < 32; ls++) {
            float xv = Xt[ls][p] * wv[ls];
            const float* br = &Bt[ls][ng * 32];
#pragma unroll
            for (int j = 0; j < 32; j += 4) {
                float4 b4 = *(const float4*)(br + j);
                acc[j + 0] = fmaf(xv, b4.x, acc[j + 0]);
                acc[j + 1] = fmaf(xv, b4.y, acc[j + 1]);
                acc[j + 2] = fmaf(xv, b4.z, acc[j + 2]);
                acc[j + 3] = fmaf(xv, b4.w, acc[j + 3]);
            }
        }
    }
    float* dst = &g_states[(((size_t)c * NH + h) * DH + p) * DS + ng * 32];
#pragma unroll
    for (int j = 0; j < 32; j += 4)
        *(float4*)(dst + j) = make_float4(acc[j], acc[j + 1], acc[j + 2], acc[j + 3]);
}

// ======================= inter-chunk carry scan (8 sequential steps) =======================
__global__ void carry_kernel() {
    int h = blockIdx.x;
    int tid = threadIdx.x;   // 256
    float carry[32];
#pragma unroll
    for (int j = 0; j < 32; j++) carry[j] = 0.f;
    for (int c = 0; c < NCH; c++) {
        float dec = __expf(g_acum[(size_t)(c * CHUNK + CHUNK - 1) * NH + h]);
        size_t off = ((size_t)c * NH + h) * DH * DS + (size_t)tid * 32;
#pragma unroll
        for (int j = 0; j < 32; j += 4) {
            float4 st = *(const float4*)&g_states[off + j];
            *(float4*)&g_prev[off + j] = make_float4(carry[j], carry[j + 1], carry[j + 2], carry[j + 3]);
            carry[j + 0] = fmaf(carry[j + 0], dec, st.x);
            carry[j + 1] = fmaf(carry[j + 1], dec, st.y);
            carry[j + 2] = fmaf(carry[j + 2], dec, st.z);
            carry[j + 3] = fmaf(carry[j + 3], dec, st.w);
        }
    }
}

// ======================= Y = intra + inter + D skip =======================
__global__ __launch_bounds__(256) void y_kernel(const float* __restrict__ Dp) {
    const int tt = blockIdx.x;   // t tile 0..3
    const int h  = blockIdx.y;
    const int c  = blockIdx.z;
    __shared__ float sM[64][68];  // M^T [s][t] (also K-tile C[t][n] in inter phase)
    __shared__ float sX[64][68];  // X   [s][p] (also K-tile prev[p][n] in inter phase)
    __shared__ float sAcT[64], sAcS[64], sDt[64], sEt[64], sEs[64];
    const int tid = threadIdx.x;
    const int tx = tid & 15, ty = tid >> 4;

    if (tid < 64)
        sAcT[tid] = g_acum[(size_t)(c * CHUNK + tt * 64 + tid) * NH + h];

    float acc[4][4] = {};

    // ---- inter-chunk: S = C(64x128) * prev^T(128x64) ----
    for (int n0 = 0; n0 < DS; n0 += 32) {
        __syncthreads();
        for (int e = tid; e < 64 * 32; e += 256) {
            int r = e >> 5, kk = e & 31;
            sM[kk][r] = g_conv[(size_t)(c * CHUNK + tt * 64 + r) * CONV_DIM + INTER + DS + n0 + kk]; // C[t][n]
            sX[kk][r] = g_prev[(((size_t)c * NH + h) * DH + r) * DS + n0 + kk];                      // prev[p][n]
        }
        __syncthreads();
#pragma unroll
        for (int k = 0; k < 32; k++) {
            float4 a = *(const float4*)&sM[k][ty * 4];
            float4 b = *(const float4*)&sX[k][tx * 4];
            float av[4] = {a.x, a.y, a.z, a.w};
            float bv[4] = {b.x, b.y, b.z, b.w};
#pragma unroll
            for (int i = 0; i < 4; i++)
#pragma unroll
                for (int j = 0; j < 4; j++)
                    acc[i][j] = fmaf(av[i], bv[j], acc[i][j]);
        }
    }
    // scale by exp(Acum_t)
#pragma unroll
    for (int i = 0; i < 4; i++) {
        float e = __expf(sAcT[ty * 4 + i]);
#pragma unroll
        for (int j = 0; j < 4; j++) acc[i][j] *= e;
    }

    // ---- intra-chunk: Y += (L o CB . diag(dt)) X, tile-factorized exps ----
    for (int st = 0; st <= tt; st++) {
        __syncthreads();
        if (tid < 64) {
            sAcS[tid] = g_acum[(size_t)(c * CHUNK + st * 64 + tid) * NH + h];
            sDt[tid]  = g_dt  [(size_t)(c * CHUNK + st * 64 + tid) * NH + h];
        }
        __syncthreads();
        if (st < tt && tid < 64) {
            float ref = sAcS[63];
            sEt[tid] = __expf(sAcT[tid] - ref);            // <= 1
            sEs[tid] = __expf(ref - sAcS[tid]) * sDt[tid]; // <= dt
        }
        __syncthreads();
        for (int e = tid; e < 64 * 64; e += 256) {
            int t = e >> 6, s = e & 63;
            float cb = g_cb[(size_t)c * CHUNK * CHUNK + (size_t)(tt * 64 + t) * CHUNK + st * 64 + s];
            float m;
            if (st < tt) m = cb * sEt[t] * sEs[s];
            else         m = (s <= t) ? cb * __expf(sAcT[t] - sAcS[s]) * sDt[s] : 0.f;
            sM[s][t] = m;
        }
        for (int e = tid; e < 64 * 64; e += 256) {
            int s = e >> 6, pp = e & 63;
            sX[s][pp] = g_conv[(size_t)(c * CHUNK + st * 64 + s) * CONV_DIM + h * DH + pp];
        }
        __syncthreads();
#pragma unroll 8
        for (int s = 0; s < 64; s++) {
            float4 a = *(const float4*)&sM[s][ty * 4];
            float4 b = *(const float4*)&sX[s][tx * 4];
            float av[4] = {a.x, a.y, a.z, a.w};
            float bv[4] = {b.x, b.y, b.z, b.w};
#pragma unroll
            for (int i = 0; i < 4; i++)
#pragma unroll
                for (int j = 0; j < 4; j++)
                    acc[i][j] = fmaf(av[i], bv[j], acc[i][j]);
        }
    }

    // D skip: sX still holds x for the s-tile == t-tile
    float dv = Dp[h];
#pragma unroll
    for (int i = 0; i < 4; i++)
#pragma unroll
        for (int j = 0; j < 4; j++)
            acc[i][j] = fmaf(dv, sX[ty * 4 + i][tx * 4 + j], acc[i][j]);

#pragma unroll
    for (int i = 0; i < 4; i++)
        *(float4*)&g_y[(size_t)(c * CHUNK + tt * 64 + ty * 4 + i) * INTER + h * DH + tx * 4] =
            make_float4(acc[i][0], acc[i][1], acc[i][2], acc[i][3]);
}

// ======================= gated RMSNorm (gate before norm) =======================
__global__ __launch_bounds__(256) void norm_kernel(const float* __restrict__ norm_w) {
    int s = blockIdx.x;
    int tid = threadIdx.x;
    float v[16];
    float ss = 0.f;
#pragma unroll
    for (int q = 0; q < 4; q++) {
        int i4 = tid + q * 256;
        float4 y4 = *(const float4*)&g_y[(size_t)s * INTER + (size_t)i4 * 4];
        float4 g4 = *(const float4*)&g_proj[(size_t)s * PROJ_DIM + (size_t)i4 * 4];
        float t0 = y4.x * (g4.x / (1.f + __expf(-g4.x)));
        float t1 = y4.y * (g4.y / (1.f + __expf(-g4.y)));
        float t2 = y4.z * (g4.z / (1.f + __expf(-g4.z)));
        float t3 = y4.w * (g4.w / (1.f + __expf(-g4.w)));
        v[q * 4 + 0] = t0; v[q * 4 + 1] = t1; v[q * 4 + 2] = t2; v[q * 4 + 3] = t3;
        ss += t0 * t0 + t1 * t1 + t2 * t2 + t3 * t3;
    }
#pragma unroll
    for (int o = 16; o > 0; o >>= 1) ss += __shfl_xor_sync(0xffffffffu, ss, o);
    __shared__ float red[8];
    if ((tid & 31) == 0) red[tid >> 5] = ss;
    __syncthreads();
    float tot = red[0] + red[1] + red[2] + red[3] + red[4] + red[5] + red[6] + red[7];
    float scale = rsqrtf(tot * (1.f / INTER) + 1e-5f);
#pragma unroll
    for (int q = 0; q < 4; q++) {
        int i4 = tid + q * 256;
        float4 w4 = *(const float4*)&norm_w[(size_t)i4 * 4];
        *(float4*)&g_y[(size_t)s * INTER + (size_t)i4 * 4] =
            make_float4(v[q * 4 + 0] * scale * w4.x, v[q * 4 + 1] * scale * w4.y,
                        v[q * 4 + 2] * scale * w4.z, v[q * 4 + 3] * scale * w4.w);
    }
}

// ======================= launch =======================
extern "C" void kernel_launch(void* const* d_in, const int* in_sizes, int n_in,
                              void* d_out, int out_size) {
    (void)in_sizes; (void)n_in; (void)out_size;
    const float* x       = (const float*)d_in[0];
    const float* W_in    = (const float*)d_in[1];
    const float* conv_w  = (const float*)d_in[2];
    const float* conv_b  = (const float*)d_in[3];
    const float* dt_bias = (const float*)d_in[4];
    const float* A_log   = (const float*)d_in[5];
    const float* Dp      = (const float*)d_in[6];
    const float* norm_w  = (const float*)d_in[7];
    const float* W_out   = (const float*)d_in[8];
    float* out = (float*)d_out;

    gemm1_kernel<<<dim3(PROJ_DIM / 64, SEQ / 128), 256>>>(x, W_in);
    conv_silu_kernel<<<(SEQ * CONV_DIM + 255) / 256, 256>>>(conv_w, conv_b);
    dt_kernel<<<(SEQ * NH) / 256, 256>>>(dt_bias);
    acum_kernel<<<NCH, 64>>>(A_log);
    cb_kernel<<<dim3(4, 4, NCH), 256>>>();
    states_kernel<<<dim3(NH, NCH), 256>>>();
    carry_kernel<<<NH, 256>>>();
    y_kernel<<<dim3(4, NH, NCH), 256>>>(Dp);
    norm_kernel<<<SEQ, 256>>>(norm_w);
    gemm2_kernel<<<dim3(HIDDEN / 64, SEQ / 128), 256>>>(W_out, out);
}

// round 12
// speedup vs baseline: 1.6858x; 1.6858x over previous
#include <cuda_runtime.h>
#include <cuda_bf16.h>
#include <stdint.h>
#include <math.h>

#define SEQ 2048
#define HIDDEN 2048
#define INTER 4096
#define NH 64
#define DH 64
#define DS 128
#define CHUNK 256
#define NCH 8
#define CONV_DIM 4352
#define PROJ_DIM 8512

// -------- scratch (device globals; no allocation allowed) --------
__device__ float g_proj[SEQ * PROJ_DIM];
__device__ float g_conv[SEQ * CONV_DIM];
__device__ float g_dt[SEQ * NH];
__device__ float g_acum[SEQ * NH];
__device__ float g_cb[NCH * CHUNK * CHUNK];
__device__ float g_states[NCH * NH * DH * DS];
__device__ float g_prev[NCH * NH * DH * DS];
__device__ float g_y[SEQ * INTER];

// bf16 split operands for tensor-core GEMMs
__device__ __nv_bfloat16 g_xh[SEQ * HIDDEN],    g_xl[SEQ * HIDDEN];
__device__ __nv_bfloat16 g_wih[PROJ_DIM * HIDDEN], g_wil[PROJ_DIM * HIDDEN];
__device__ __nv_bfloat16 g_yh[SEQ * INTER],     g_yl[SEQ * INTER];
__device__ __nv_bfloat16 g_woh[HIDDEN * INTER], g_wol[HIDDEN * INTER];

// ======================= helpers =======================
__device__ __forceinline__ uint32_t smem_u32(const void* p) {
    uint32_t a;
    asm("{ .reg .u64 t; cvta.to.shared.u64 t, %1; cvt.u32.u64 %0, t; }" : "=r"(a) : "l"(p));
    return a;
}

#define LDSM4(r, a) \
    asm volatile("ldmatrix.sync.aligned.m8n8.x4.shared.b16 {%0,%1,%2,%3}, [%4];" \
        : "=r"((r)[0]), "=r"((r)[1]), "=r"((r)[2]), "=r"((r)[3]) : "r"(a))

#define MMA16816(c, a, b) \
    asm volatile("mma.sync.aligned.m16n8k16.row.col.f32.bf16.bf16.f32 " \
        "{%0,%1,%2,%3}, {%4,%5,%6,%7}, {%8,%9}, {%0,%1,%2,%3};" \
        : "+f"((c)[0]), "+f"((c)[1]), "+f"((c)[2]), "+f"((c)[3]) \
        : "r"((a)[0]), "r"((a)[1]), "r"((a)[2]), "r"((a)[3]), "r"((b)[0]), "r"((b)[1]))

__device__ __forceinline__ void cp16(uint32_t dst, const void* src) {
    unsigned long long g = (unsigned long long)__cvta_generic_to_global(src);
    asm volatile("cp.async.cg.shared.global [%0], [%1], 16;" :: "r"(dst), "l"(g));
}

// ======================= fp32 -> bf16 hi/lo split =======================
__global__ void split_kernel(const float* __restrict__ in, __nv_bfloat16* __restrict__ hi,
                             __nv_bfloat16* __restrict__ lo, int n) {
    int i = (blockIdx.x * blockDim.x + threadIdx.x) * 4;
    if (i >= n) return;
    float4 v = *(const float4*)(in + i);
    __nv_bfloat16 h0 = __float2bfloat16(v.x), h1 = __float2bfloat16(v.y);
    __nv_bfloat16 h2 = __float2bfloat16(v.z), h3 = __float2bfloat16(v.w);
    __nv_bfloat16 l0 = __float2bfloat16(v.x - __bfloat162float(h0));
    __nv_bfloat16 l1 = __float2bfloat16(v.y - __bfloat162float(h1));
    __nv_bfloat16 l2 = __float2bfloat16(v.z - __bfloat162float(h2));
    __nv_bfloat16 l3 = __float2bfloat16(v.w - __bfloat162float(h3));
    *(__nv_bfloat162*)(hi + i)     = __nv_bfloat162(h0, h1);
    *(__nv_bfloat162*)(hi + i + 2) = __nv_bfloat162(h2, h3);
    *(__nv_bfloat162*)(lo + i)     = __nv_bfloat162(l0, l1);
    *(__nv_bfloat162*)(lo + i + 2) = __nv_bfloat162(l2, l3);
}

// ======================= mma.sync GEMM: C[M, slice] = A[M,K] * B[N,K]^T =======================
// smem row pitch 40 bf16 (80B) -> conflict-free ldmatrix; 3-stage cp.async pipeline.
#define PITCH 40

template<int K, int NT>
__device__ __forceinline__ void issue_tile(uint32_t st, int t, int bm, int bn,
        const __nv_bfloat16* __restrict__ Ah, const __nv_bfloat16* __restrict__ Al,
        const __nv_bfloat16* __restrict__ Bh, const __nv_bfloat16* __restrict__ Bl,
        int tid) {
    constexpr int ABYTES = 128 * PITCH * 2;
    constexpr int BBYTES = NT * PITCH * 2;
    const int kt = t * 32;
#pragma unroll
    for (int i = 0; i < 2; i++) {
        int cid = tid + i * 256;
        int r = cid >> 2, q = cid & 3;
        size_t src = (size_t)(bm + r) * K + kt + q * 8;
        uint32_t d = st + (uint32_t)(r * PITCH + q * 8) * 2;
        cp16(d, Ah + src);
        cp16(d + ABYTES, Al + src);
    }
#pragma unroll
    for (int i = 0; i < NT / 64; i++) {
        int cid = tid + i * 256;
        int r = cid >> 2, q = cid & 3;
        size_t src = (size_t)(bn + r) * K + kt + q * 8;
        uint32_t d = st + 2 * ABYTES + (uint32_t)(r * PITCH + q * 8) * 2;
        cp16(d, Bh + src);
        cp16(d + BBYTES, Bl + src);
    }
}

template<int K, int NS, int NT>
__global__ __launch_bounds__(256, 1) void gemm_mma_kernel(
        const __nv_bfloat16* __restrict__ Ah, const __nv_bfloat16* __restrict__ Al,
        const __nv_bfloat16* __restrict__ Bh, const __nv_bfloat16* __restrict__ Bl,
        float* __restrict__ C, int n0) {
    extern __shared__ char smem[];
    constexpr int ABYTES = 128 * PITCH * 2;
    constexpr int BBYTES = NT * PITCH * 2;
    constexpr int STAGE = 2 * ABYTES + 2 * BBYTES;
    constexpr int T = K / 32;
    constexpr int WNF = NT / 16;   // n8 frags per warp (warps are 4x2)

    const int tid = threadIdx.x;
    const int lane = tid & 31, wid = tid >> 5;
    const int wm = wid & 3, wn = wid >> 2;
    const int bm = blockIdx.y * 128;
    const int bn = n0 + blockIdx.x * NT;
    const uint32_t sb = smem_u32(smem);

    float acc[2][WNF][4];
#pragma unroll
    for (int i = 0; i < 2; i++)
#pragma unroll
        for (int j = 0; j < WNF; j++)
#pragma unroll
            for (int q = 0; q < 4; q++) acc[i][j][q] = 0.f;

    issue_tile<K, NT>(sb, 0, bm, bn, Ah, Al, Bh, Bl, tid);
    asm volatile("cp.async.commit_group;" ::: "memory");
    issue_tile<K, NT>(sb + STAGE, 1, bm, bn, Ah, Al, Bh, Bl, tid);
    asm volatile("cp.async.commit_group;" ::: "memory");

    // lane-invariant ldmatrix address pieces
    const int lrow = lane & 15;
    const int lcol = (lane >> 4) * 8;
    const uint32_t aoff = (uint32_t)((wm * 32 + lrow) * PITCH + lcol) * 2;
    const uint32_t boff = 2 * ABYTES + (uint32_t)((wn * (WNF * 8) + lrow) * PITCH + lcol) * 2;

    for (int t = 0; t < T; t++) {
        asm volatile("cp.async.wait_group 1;" ::: "memory");
        __syncthreads();
        const uint32_t stg = sb + (uint32_t)(t % 3) * STAGE;
#pragma unroll
        for (int kk = 0; kk < 32; kk += 16) {
            uint32_t ah[2][4], al[2][4];
#pragma unroll
            for (int fm = 0; fm < 2; fm++) {
                uint32_t ad = stg + aoff + (uint32_t)(fm * 16 * PITCH + kk) * 2;
                LDSM4(ah[fm], ad);
                LDSM4(al[fm], ad + ABYTES);
            }
            uint32_t bh[WNF][2], bl[WNF][2];
#pragma unroll
            for (int g = 0; g < WNF / 2; g++) {
                uint32_t bd = stg + boff + (uint32_t)(g * 16 * PITCH + kk) * 2;
                uint32_t r[4];
                LDSM4(r, bd);
                bh[2 * g][0] = r[0]; bh[2 * g + 1][0] = r[1];
                bh[2 * g][1] = r[2]; bh[2 * g + 1][1] = r[3];
                LDSM4(r, bd + BBYTES);
                bl[2 * g][0] = r[0]; bl[2 * g + 1][0] = r[1];
                bl[2 * g][1] = r[2]; bl[2 * g + 1][1] = r[3];
            }
#pragma unroll
            for (int fm = 0; fm < 2; fm++)
#pragma unroll
                for (int fn = 0; fn < WNF; fn++) {
                    MMA16816(acc[fm][fn], ah[fm], bh[fn]);
                    MMA16816(acc[fm][fn], ah[fm], bl[fn]);
                    MMA16816(acc[fm][fn], al[fm], bh[fn]);
                }
        }
        if (t + 2 < T)
            issue_tile<K, NT>(sb + (uint32_t)((t + 2) % 3) * STAGE, t + 2, bm, bn, Ah, Al, Bh, Bl, tid);
        asm volatile("cp.async.commit_group;" ::: "memory");
    }

    const int crow = lane >> 2, ccol = (lane & 3) * 2;
#pragma unroll
    for (int fm = 0; fm < 2; fm++)
#pragma unroll
        for (int fn = 0; fn < WNF; fn++) {
            int m = bm + wm * 32 + fm * 16 + crow;
            int n = bn + wn * (WNF * 8) + fn * 8 + ccol;
            *(float2*)&C[(size_t)m * NS + n]       = make_float2(acc[fm][fn][0], acc[fm][fn][1]);
            *(float2*)&C[(size_t)(m + 8) * NS + n] = make_float2(acc[fm][fn][2], acc[fm][fn][3]);
        }
}

// ======================= depthwise causal conv (K=4) + SiLU =======================
__global__ void conv_silu_kernel(const float* __restrict__ conv_w,
                                 const float* __restrict__ conv_b) {
    int idx = blockIdx.x * blockDim.x + threadIdx.x;
    if (idx >= SEQ * CONV_DIM) return;
    int s = idx / CONV_DIM;
    int c = idx - s * CONV_DIM;
    float w0 = conv_w[c * 4 + 0], w1 = conv_w[c * 4 + 1];
    float w2 = conv_w[c * 4 + 2], w3 = conv_w[c * 4 + 3];
    const float* col = g_proj + INTER + c;
    float acc = conv_b[c];
    if (s >= 3) acc = fmaf(col[(size_t)(s - 3) * PROJ_DIM], w0, acc);
    if (s >= 2) acc = fmaf(col[(size_t)(s - 2) * PROJ_DIM], w1, acc);
    if (s >= 1) acc = fmaf(col[(size_t)(s - 1) * PROJ_DIM], w2, acc);
    acc = fmaf(col[(size_t)s * PROJ_DIM], w3, acc);
    float sig = 1.f / (1.f + __expf(-acc));
    g_conv[idx] = acc * sig;
}

// ======================= dt = softplus(dt_raw + dt_bias) =======================
__global__ void dt_kernel(const float* __restrict__ dt_bias) {
    int idx = blockIdx.x * blockDim.x + threadIdx.x;
    int h = idx & 63;
    int s = idx >> 6;
    float v = g_proj[(size_t)s * PROJ_DIM + (INTER + CONV_DIM) + h] + dt_bias[h];
    g_dt[idx] = (v > 20.f) ? v : log1pf(__expf(v));
}

// ======================= per-chunk cumsum(dt*A): warp scan per (c,h) =======================
__global__ void acum_kernel(const float* __restrict__ A_log) {
    int wg = blockIdx.x * 8 + (threadIdx.x >> 5);
    int lane = threadIdx.x & 31;
    int c = wg >> 6, h = wg & 63;
    float A = -__expf(A_log[h]);
    const float* dtp = g_dt + ((size_t)c * CHUNK) * NH + h;
    float v[8];
    float run = 0.f;
#pragma unroll
    for (int j = 0; j < 8; j++) {
        v[j] = dtp[(size_t)(lane * 8 + j) * NH] * A;
        run += v[j];
    }
    float s = run;
#pragma unroll
    for (int o = 1; o < 32; o <<= 1) {
        float t = __shfl_up_sync(0xffffffffu, s, o);
        if (lane >= o) s += t;
    }
    float acc = s - run;
    float* acp = g_acum + ((size_t)c * CHUNK) * NH + h;
#pragma unroll
    for (int j = 0; j < 8; j++) {
        acc += v[j];
        acp[(size_t)(lane * 8 + j) * NH] = acc;
    }
}

// ======================= CB[c][t][s] = C_t . B_s (shared over heads), s<=t tiles only =======================
__global__ __launch_bounds__(256) void cb_kernel() {
    int st = blockIdx.x, tt = blockIdx.y, c = blockIdx.z;
    if (st > tt) return;
    __shared__ float Cs[32][68];
    __shared__ float Bs2[32][68];
    const int tid = threadIdx.x;
    const int tx = tid & 15, ty = tid >> 4;
    float acc[4][4] = {};
    for (int n0 = 0; n0 < DS; n0 += 32) {
        __syncthreads();
        for (int e = tid; e < 64 * 32; e += 256) {
            int r = e >> 5, kk = e & 31;
            Cs[kk][r]  = g_conv[(size_t)(c * CHUNK + tt * 64 + r) * CONV_DIM + INTER + DS + n0 + kk];
            Bs2[kk][r] = g_conv[(size_t)(c * CHUNK + st * 64 + r) * CONV_DIM + INTER + n0 + kk];
        }
        __syncthreads();
#pragma unroll
        for (int k = 0; k < 32; k++) {
            float4 a = *(const float4*)&Cs[k][ty * 4];
            float4 b = *(const float4*)&Bs2[k][tx * 4];
            float av[4] = {a.x, a.y, a.z, a.w};
            float bv[4] = {b.x, b.y, b.z, b.w};
#pragma unroll
            for (int i = 0; i < 4; i++)
#pragma unroll
                for (int j = 0; j < 4; j++)
                    acc[i][j] = fmaf(av[i], bv[j], acc[i][j]);
        }
    }
#pragma unroll
    for (int i = 0; i < 4; i++)
        *(float4*)&g_cb[(size_t)c * CHUNK * CHUNK + (size_t)(tt * 64 + ty * 4 + i) * CHUNK + st * 64 + tx * 4] =
            make_float4(acc[i][0], acc[i][1], acc[i][2], acc[i][3]);
}

// ======================= chunk end states: states[c][h][p][n] =======================
__global__ __launch_bounds__(256) void states_kernel() {
    int h = blockIdx.x, c = blockIdx.y;
    __shared__ float Bt[32][DS];
    __shared__ float Xt[32][DH];
    __shared__ float wv[32];
    const int tid = threadIdx.x;
    const int p = tid >> 2, ng = tid & 3;
    float acc[32];
#pragma unroll
    for (int j = 0; j < 32; j++) acc[j] = 0.f;
    float Aend = g_acum[(size_t)(c * CHUNK + CHUNK - 1) * NH + h];
    for (int lt = 0; lt < 8; lt++) {
        __syncthreads();
        for (int e = tid; e < 32 * DS; e += 256) {
            int r = e >> 7, n = e & 127;
            Bt[r][n] = g_conv[(size_t)(c * CHUNK + lt * 32 + r) * CONV_DIM + INTER + n];
        }
        for (int e = tid; e < 32 * DH; e += 256) {
            int r = e >> 6, pp = e & 63;
            Xt[r][pp] = g_conv[(size_t)(c * CHUNK + lt * 32 + r) * CONV_DIM + h * DH + pp];
        }
        if (tid < 32) {
            int l = lt * 32 + tid;
            float ac = g_acum[(size_t)(c * CHUNK + l) * NH + h];
            wv[tid] = __expf(Aend - ac) * g_dt[(size_t)(c * CHUNK + l) * NH + h];
        }
        __syncthreads();
#pragma unroll 4
        for (int ls = 0; ls < 32; ls++) {
            float xv = Xt[ls][p] * wv[ls];
            const float* br = &Bt[ls][ng * 32];
#pragma unroll
            for (int j = 0; j < 32; j += 4) {
                float4 b4 = *(const float4*)(br + j);
                acc[j + 0] = fmaf(xv, b4.x, acc[j + 0]);
                acc[j + 1] = fmaf(xv, b4.y, acc[j + 1]);
                acc[j + 2] = fmaf(xv, b4.z, acc[j + 2]);
                acc[j + 3] = fmaf(xv, b4.w, acc[j + 3]);
            }
        }
    }
    float* dst = &g_states[(((size_t)c * NH + h) * DH + p) * DS + ng * 32];
#pragma unroll
    for (int j = 0; j < 32; j += 4)
        *(float4*)(dst + j) = make_float4(acc[j], acc[j + 1], acc[j + 2], acc[j + 3]);
}

// ======================= inter-chunk carry scan =======================
__global__ void carry_kernel() {
    int h = blockIdx.x;
    int tid = threadIdx.x;
    float carry[32];
#pragma unroll
    for (int j = 0; j < 32; j++) carry[j] = 0.f;
    for (int c = 0; c < NCH; c++) {
        float dec = __expf(g_acum[(size_t)(c * CHUNK + CHUNK - 1) * NH + h]);
        size_t off = ((size_t)c * NH + h) * DH * DS + (size_t)tid * 32;
#pragma unroll
        for (int j = 0; j < 32; j += 4) {
            float4 st = *(const float4*)&g_states[off + j];
            *(float4*)&g_prev[off + j] = make_float4(carry[j], carry[j + 1], carry[j + 2], carry[j + 3]);
            carry[j + 0] = fmaf(carry[j + 0], dec, st.x);
            carry[j + 1] = fmaf(carry[j + 1], dec, st.y);
            carry[j + 2] = fmaf(carry[j + 2], dec, st.z);
            carry[j + 3] = fmaf(carry[j + 3], dec, st.w);
        }
    }
}

// ======================= Y = intra + inter + D skip =======================
__global__ __launch_bounds__(256) void y_kernel(const float* __restrict__ Dp) {
    const int tt = blockIdx.x;
    const int h  = blockIdx.y;
    const int c  = blockIdx.z;
    __shared__ float sM[64][68];
    __shared__ float sX[64][68];
    __shared__ float sAcT[64], sAcS[64], sDt[64], sEt[64], sEs[64];
    const int tid = threadIdx.x;
    const int tx = tid & 15, ty = tid >> 4;

    if (tid < 64)
        sAcT[tid] = g_acum[(size_t)(c * CHUNK + tt * 64 + tid) * NH + h];

    float acc[4][4] = {};

    for (int n0 = 0; n0 < DS; n0 += 32) {
        __syncthreads();
        for (int e = tid; e < 64 * 32; e += 256) {
            int r = e >> 5, kk = e & 31;
            sM[kk][r] = g_conv[(size_t)(c * CHUNK + tt * 64 + r) * CONV_DIM + INTER + DS + n0 + kk];
            sX[kk][r] = g_prev[(((size_t)c * NH + h) * DH + r) * DS + n0 + kk];
        }
        __syncthreads();
#pragma unroll
        for (int k = 0; k < 32; k++) {
            float4 a = *(const float4*)&sM[k][ty * 4];
            float4 b = *(const float4*)&sX[k][tx * 4];
            float av[4] = {a.x, a.y, a.z, a.w};
            float bv[4] = {b.x, b.y, b.z, b.w};
#pragma unroll
            for (int i = 0; i < 4; i++)
#pragma unroll
                for (int j = 0; j < 4; j++)
                    acc[i][j] = fmaf(av[i], bv[j], acc[i][j]);
        }
    }
#pragma unroll
    for (int i = 0; i < 4; i++) {
        float e = __expf(sAcT[ty * 4 + i]);
#pragma unroll
        for (int j = 0; j < 4; j++) acc[i][j] *= e;
    }

    for (int st = 0; st <= tt; st++) {
        __syncthreads();
        if (tid < 64) {
            sAcS[tid] = g_acum[(size_t)(c * CHUNK + st * 64 + tid) * NH + h];
            sDt[tid]  = g_dt  [(size_t)(c * CHUNK + st * 64 + tid) * NH + h];
        }
        __syncthreads();
        if (st < tt && tid < 64) {
            float ref = sAcS[63];
            sEt[tid] = __expf(sAcT[tid] - ref);
            sEs[tid] = __expf(ref - sAcS[tid]) * sDt[tid];
        }
        __syncthreads();
        for (int e = tid; e < 64 * 64; e += 256) {
            int t = e >> 6, s = e & 63;
            float cb = g_cb[(size_t)c * CHUNK * CHUNK + (size_t)(tt * 64 + t) * CHUNK + st * 64 + s];
            float m;
            if (st < tt) m = cb * sEt[t] * sEs[s];
            else         m = (s <= t) ? cb * __expf(sAcT[t] - sAcS[s]) * sDt[s] : 0.f;
            sM[s][t] = m;
        }
        for (int e = tid; e < 64 * 64; e += 256) {
            int s = e >> 6, pp = e & 63;
            sX[s][pp] = g_conv[(size_t)(c * CHUNK + st * 64 + s) * CONV_DIM + h * DH + pp];
        }
        __syncthreads();
#pragma unroll 8
        for (int s = 0; s < 64; s++) {
            float4 a = *(const float4*)&sM[s][ty * 4];
            float4 b = *(const float4*)&sX[s][tx * 4];
            float av[4] = {a.x, a.y, a.z, a.w};
            float bv[4] = {b.x, b.y, b.z, b.w};
#pragma unroll
            for (int i = 0; i < 4; i++)
#pragma unroll
                for (int j = 0; j < 4; j++)
                    acc[i][j] = fmaf(av[i], bv[j], acc[i][j]);
        }
    }

    float dv = Dp[h];
#pragma unroll
    for (int i = 0; i < 4; i++)
#pragma unroll
        for (int j = 0; j < 4; j++)
            acc[i][j] = fmaf(dv, sX[ty * 4 + i][tx * 4 + j], acc[i][j]);

#pragma unroll
    for (int i = 0; i < 4; i++)
        *(float4*)&g_y[(size_t)(c * CHUNK + tt * 64 + ty * 4 + i) * INTER + h * DH + tx * 4] =
            make_float4(acc[i][0], acc[i][1], acc[i][2], acc[i][3]);
}

// ======================= gated RMSNorm -> bf16 split output =======================
__global__ __launch_bounds__(256) void norm_kernel(const float* __restrict__ norm_w) {
    int s = blockIdx.x;
    int tid = threadIdx.x;
    float v[16];
    float ss = 0.f;
#pragma unroll
    for (int q = 0; q < 4; q++) {
        int i4 = tid + q * 256;
        float4 y4 = *(const float4*)&g_y[(size_t)s * INTER + (size_t)i4 * 4];
        float4 g4 = *(const float4*)&g_proj[(size_t)s * PROJ_DIM + (size_t)i4 * 4];
        float t0 = y4.x * (g4.x / (1.f + __expf(-g4.x)));
        float t1 = y4.y * (g4.y / (1.f + __expf(-g4.y)));
        float t2 = y4.z * (g4.z / (1.f + __expf(-g4.z)));
        float t3 = y4.w * (g4.w / (1.f + __expf(-g4.w)));
        v[q * 4 + 0] = t0; v[q * 4 + 1] = t1; v[q * 4 + 2] = t2; v[q * 4 + 3] = t3;
        ss += t0 * t0 + t1 * t1 + t2 * t2 + t3 * t3;
    }
#pragma unroll
    for (int o = 16; o > 0; o >>= 1) ss += __shfl_xor_sync(0xffffffffu, ss, o);
    __shared__ float red[8];
    if ((tid & 31) == 0) red[tid >> 5] = ss;
    __syncthreads();
    float tot = red[0] + red[1] + red[2] + red[3] + red[4] + red[5] + red[6] + red[7];
    float scale = rsqrtf(tot * (1.f / INTER) + 1e-5f);
#pragma unroll
    for (int q = 0; q < 4; q++) {
        int i4 = tid + q * 256;
        float4 w4 = *(const float4*)&norm_w[(size_t)i4 * 4];
        float o0 = v[q * 4 + 0] * scale * w4.x;
        float o1 = v[q * 4 + 1] * scale * w4.y;
        float o2 = v[q * 4 + 2] * scale * w4.z;
        float o3 = v[q * 4 + 3] * scale * w4.w;
        __nv_bfloat16 h0 = __float2bfloat16(o0), h1 = __float2bfloat16(o1);
        __nv_bfloat16 h2 = __float2bfloat16(o2), h3 = __float2bfloat16(o3);
        __nv_bfloat16 l0 = __float2bfloat16(o0 - __bfloat162float(h0));
        __nv_bfloat16 l1 = __float2bfloat16(o1 - __bfloat162float(h1));
        __nv_bfloat16 l2 = __float2bfloat16(o2 - __bfloat162float(h2));
        __nv_bfloat16 l3 = __float2bfloat16(o3 - __bfloat162float(h3));
        size_t base = (size_t)s * INTER + (size_t)i4 * 4;
        *(__nv_bfloat162*)(g_yh + base)     = __nv_bfloat162(h0, h1);
        *(__nv_bfloat162*)(g_yh + base + 2) = __nv_bfloat162(h2, h3);
        *(__nv_bfloat162*)(g_yl + base)     = __nv_bfloat162(l0, l1);
        *(__nv_bfloat162*)(g_yl + base + 2) = __nv_bfloat162(l2, l3);
    }
}

// ======================= launch =======================
extern "C" void kernel_launch(void* const* d_in, const int* in_sizes, int n_in,
                              void* d_out, int out_size) {
    (void)in_sizes; (void)n_in; (void)out_size;
    const float* x       = (const float*)d_in[0];
    const float* W_in    = (const float*)d_in[1];
    const float* conv_w  = (const float*)d_in[2];
    const float* conv_b  = (const float*)d_in[3];
    const float* dt_bias = (const float*)d_in[4];
    const float* A_log   = (const float*)d_in[5];
    const float* Dp      = (const float*)d_in[6];
    const float* norm_w  = (const float*)d_in[7];
    const float* W_out   = (const float*)d_in[8];
    float* out = (float*)d_out;

    // stage sizes: NT=128 -> 40960B, NT=64 -> 30720B; 3 stages each
    const int SM128 = 3 * (2 * 128 * PITCH * 2 + 2 * 128 * PITCH * 2); // 122880
    const int SM64  = 3 * (2 * 128 * PITCH * 2 + 2 * 64 * PITCH * 2);  // 92160
    cudaFuncSetAttribute(gemm_mma_kernel<HIDDEN, PROJ_DIM, 128>,
                         cudaFuncAttributeMaxDynamicSharedMemorySize, SM128);
    cudaFuncSetAttribute(gemm_mma_kernel<HIDDEN, PROJ_DIM, 64>,
                         cudaFuncAttributeMaxDynamicSharedMemorySize, SM64);
    cudaFuncSetAttribute(gemm_mma_kernel<INTER, HIDDEN, 128>,
                         cudaFuncAttributeMaxDynamicSharedMemorySize, SM128);

    __nv_bfloat16 *xh, *xl, *wih, *wil, *yh, *yl, *woh, *wol;
    cudaGetSymbolAddress((void**)&xh,  g_xh);  cudaGetSymbolAddress((void**)&xl,  g_xl);
    cudaGetSymbolAddress((void**)&wih, g_wih); cudaGetSymbolAddress((void**)&wil, g_wil);
    cudaGetSymbolAddress((void**)&yh,  g_yh);  cudaGetSymbolAddress((void**)&yl,  g_yl);
    cudaGetSymbolAddress((void**)&woh, g_woh); cudaGetSymbolAddress((void**)&wol, g_wol);
    float* proj; cudaGetSymbolAddress((void**)&proj, g_proj);

    split_kernel<<<(SEQ * HIDDEN / 4 + 255) / 256, 256>>>(x, xh, xl, SEQ * HIDDEN);
    split_kernel<<<(PROJ_DIM * HIDDEN / 4 + 255) / 256, 256>>>(W_in, wih, wil, PROJ_DIM * HIDDEN);
    split_kernel<<<(HIDDEN * INTER / 4 + 255) / 256, 256>>>(W_out, woh, wol, HIDDEN * INTER);

    gemm_mma_kernel<HIDDEN, PROJ_DIM, 128><<<dim3(66, 16), 256, SM128>>>(xh, xl, wih, wil, proj, 0);
    gemm_mma_kernel<HIDDEN, PROJ_DIM, 64><<<dim3(1, 16), 256, SM64>>>(xh, xl, wih, wil, proj, 8448);

    conv_silu_kernel<<<(SEQ * CONV_DIM + 255) / 256, 256>>>(conv_w, conv_b);
    dt_kernel<<<(SEQ * NH) / 256, 256>>>(dt_bias);
    acum_kernel<<<64, 256>>>(A_log);
    cb_kernel<<<dim3(4, 4, NCH), 256>>>();
    states_kernel<<<dim3(NH, NCH), 256>>>();
    carry_kernel<<<NH, 256>>>();
    y_kernel<<<dim3(4, NH, NCH), 256>>>(Dp);
    norm_kernel<<<SEQ, 256>>>(norm_w);

    gemm_mma_kernel<INTER, HIDDEN, 128><<<dim3(16, 16), 256, SM128>>>(yh, yl, woh, wol, out, 0);
}

// round 13
// speedup vs baseline: 1.7526x; 1.0396x over previous
#include <cuda_runtime.h>
#include <cuda_bf16.h>
#include <stdint.h>
#include <math.h>

#define SEQ 2048
#define HIDDEN 2048
#define INTER 4096
#define NH 64
#define DH 64
#define DS 128
#define CHUNK 256
#define NCH 8
#define CONV_DIM 4352
#define PROJ_DIM 8512

// -------- scratch (device globals; no allocation allowed) --------
__device__ float g_proj[SEQ * PROJ_DIM];
__device__ float g_conv[SEQ * CONV_DIM];
__device__ float g_dt[SEQ * NH];
__device__ float g_acum[SEQ * NH];
__device__ float g_cb[NCH * CHUNK * CHUNK];
__device__ float g_states[NCH * NH * DH * DS];
__device__ float g_prev[NCH * NH * DH * DS];
__device__ float g_y[SEQ * INTER];

// bf16 split operands for tensor-core GEMMs
__device__ __nv_bfloat16 g_xh[SEQ * HIDDEN],    g_xl[SEQ * HIDDEN];
__device__ __nv_bfloat16 g_wih[PROJ_DIM * HIDDEN], g_wil[PROJ_DIM * HIDDEN];
__device__ __nv_bfloat16 g_yh[SEQ * INTER],     g_yl[SEQ * INTER];
__device__ __nv_bfloat16 g_woh[HIDDEN * INTER], g_wol[HIDDEN * INTER];

// ======================= helpers =======================
__device__ __forceinline__ uint32_t smem_u32(const void* p) {
    uint32_t a;
    asm("{ .reg .u64 t; cvta.to.shared.u64 t, %1; cvt.u32.u64 %0, t; }" : "=r"(a) : "l"(p));
    return a;
}

#define LDSM4(r, a) \
    asm volatile("ldmatrix.sync.aligned.m8n8.x4.shared.b16 {%0,%1,%2,%3}, [%4];" \
        : "=r"((r)[0]), "=r"((r)[1]), "=r"((r)[2]), "=r"((r)[3]) : "r"(a))

#define MMA16816(c, a, b0, b1) \
    asm volatile("mma.sync.aligned.m16n8k16.row.col.f32.bf16.bf16.f32 " \
        "{%0,%1,%2,%3}, {%4,%5,%6,%7}, {%8,%9}, {%0,%1,%2,%3};" \
        : "+f"((c)[0]), "+f"((c)[1]), "+f"((c)[2]), "+f"((c)[3]) \
        : "r"((a)[0]), "r"((a)[1]), "r"((a)[2]), "r"((a)[3]), "r"(b0), "r"(b1))

__device__ __forceinline__ void cp16(uint32_t dst, const void* src) {
    unsigned long long g = (unsigned long long)__cvta_generic_to_global(src);
    asm volatile("cp.async.cg.shared.global [%0], [%1], 16;" :: "r"(dst), "l"(g));
}

// ======================= fp32 -> bf16 hi/lo split =======================
__global__ void split_kernel(const float* __restrict__ in, __nv_bfloat16* __restrict__ hi,
                             __nv_bfloat16* __restrict__ lo, int n) {
    int i = (blockIdx.x * blockDim.x + threadIdx.x) * 4;
    if (i >= n) return;
    float4 v = *(const float4*)(in + i);
    __nv_bfloat16 h0 = __float2bfloat16(v.x), h1 = __float2bfloat16(v.y);
    __nv_bfloat16 h2 = __float2bfloat16(v.z), h3 = __float2bfloat16(v.w);
    __nv_bfloat16 l0 = __float2bfloat16(v.x - __bfloat162float(h0));
    __nv_bfloat16 l1 = __float2bfloat16(v.y - __bfloat162float(h1));
    __nv_bfloat16 l2 = __float2bfloat16(v.z - __bfloat162float(h2));
    __nv_bfloat16 l3 = __float2bfloat16(v.w - __bfloat162float(h3));
    *(__nv_bfloat162*)(hi + i)     = __nv_bfloat162(h0, h1);
    *(__nv_bfloat162*)(hi + i + 2) = __nv_bfloat162(h2, h3);
    *(__nv_bfloat162*)(lo + i)     = __nv_bfloat162(l0, l1);
    *(__nv_bfloat162*)(lo + i + 2) = __nv_bfloat162(l2, l3);
}

// ======================= mma.sync GEMM: C[M, slice] = A[M,K] * B[N,K]^T =======================
// CTA 128 x NT (NT=256 main / 64 tail), 512 threads (warps 4x4), 3-stage cp.async.
// smem row pitch 40 bf16 (80B) -> conflict-free ldmatrix.
#define PITCH 40

template<int K, int NT>
__device__ __forceinline__ void issue_tile(uint32_t st, int t, int bm, int bn,
        const __nv_bfloat16* __restrict__ Ah, const __nv_bfloat16* __restrict__ Al,
        const __nv_bfloat16* __restrict__ Bh, const __nv_bfloat16* __restrict__ Bl,
        int tid) {
    constexpr int ABYTES = 128 * PITCH * 2;
    constexpr int BBYTES = NT * PITCH * 2;
    const int kt = t * 32;
    {   // A: 128 rows x 4 chunks = 512 chunks (one per thread)
        int r = tid >> 2, q = tid & 3;
        size_t src = (size_t)(bm + r) * K + kt + q * 8;
        uint32_t d = st + (uint32_t)(r * PITCH + q * 8) * 2;
        cp16(d, Ah + src);
        cp16(d + ABYTES, Al + src);
    }
    constexpr int BCH = NT * 4;
#pragma unroll
    for (int i = 0; i < (BCH + 511) / 512; i++) {
        int cid = tid + i * 512;
        if ((BCH % 512 == 0) || cid < BCH) {
            int r = cid >> 2, q = cid & 3;
            size_t src = (size_t)(bn + r) * K + kt + q * 8;
            uint32_t d = st + 2 * ABYTES + (uint32_t)(r * PITCH + q * 8) * 2;
            cp16(d, Bh + src);
            cp16(d + BBYTES, Bl + src);
        }
    }
}

template<int K, int NS, int NT>
__global__ __launch_bounds__(512, 1) void gemm_mma_kernel(
        const __nv_bfloat16* __restrict__ Ah, const __nv_bfloat16* __restrict__ Al,
        const __nv_bfloat16* __restrict__ Bh, const __nv_bfloat16* __restrict__ Bl,
        float* __restrict__ C, int n0) {
    extern __shared__ char smem[];
    constexpr int ABYTES = 128 * PITCH * 2;
    constexpr int BBYTES = NT * PITCH * 2;
    constexpr int STAGE = 2 * ABYTES + 2 * BBYTES;
    constexpr int T = K / 32;
    constexpr int WNF = NT / 32;        // n8 frags per warp (4 n-warps)
    constexpr int WSPAN = NT / 4;       // cols per warp

    const int tid = threadIdx.x;
    const int lane = tid & 31, wid = tid >> 5;
    const int wm = wid & 3, wn = wid >> 2;
    const int bm = blockIdx.y * 128;
    const int bn = n0 + blockIdx.x * NT;
    const uint32_t sb = smem_u32(smem);

    float acc[2][WNF][4];
#pragma unroll
    for (int i = 0; i < 2; i++)
#pragma unroll
        for (int j = 0; j < WNF; j++)
#pragma unroll
            for (int q = 0; q < 4; q++) acc[i][j][q] = 0.f;

    issue_tile<K, NT>(sb, 0, bm, bn, Ah, Al, Bh, Bl, tid);
    asm volatile("cp.async.commit_group;" ::: "memory");
    issue_tile<K, NT>(sb + STAGE, 1, bm, bn, Ah, Al, Bh, Bl, tid);
    asm volatile("cp.async.commit_group;" ::: "memory");

    const int lrow = lane & 15;
    const int lcol = (lane >> 4) * 8;
    const uint32_t aoff = (uint32_t)((wm * 32 + lrow) * PITCH + lcol) * 2;
    const uint32_t boff = 2 * ABYTES + (uint32_t)((wn * WSPAN + lrow) * PITCH + lcol) * 2;

    for (int t = 0; t < T; t++) {
        asm volatile("cp.async.wait_group 1;" ::: "memory");
        __syncthreads();
        const uint32_t stg = sb + (uint32_t)(t % 3) * STAGE;
#pragma unroll
        for (int kk = 0; kk < 32; kk += 16) {
            uint32_t ah[2][4], al[2][4];
#pragma unroll
            for (int fm = 0; fm < 2; fm++) {
                uint32_t ad = stg + aoff + (uint32_t)(fm * 16 * PITCH + kk) * 2;
                LDSM4(ah[fm], ad);
                LDSM4(al[fm], ad + ABYTES);
            }
#pragma unroll
            for (int g = 0; g < WNF / 2; g++) {
                uint32_t bd = stg + boff + (uint32_t)(g * 16 * PITCH + kk) * 2;
                uint32_t rh[4], rl[4];
                LDSM4(rh, bd);
                LDSM4(rl, bd + BBYTES);
                // product 1: ah * bh
#pragma unroll
                for (int fm = 0; fm < 2; fm++) {
                    MMA16816(acc[fm][2 * g],     ah[fm], rh[0], rh[2]);
                    MMA16816(acc[fm][2 * g + 1], ah[fm], rh[1], rh[3]);
                }
                // product 2: ah * bl
#pragma unroll
                for (int fm = 0; fm < 2; fm++) {
                    MMA16816(acc[fm][2 * g],     ah[fm], rl[0], rl[2]);
                    MMA16816(acc[fm][2 * g + 1], ah[fm], rl[1], rl[3]);
                }
                // product 3: al * bh
#pragma unroll
                for (int fm = 0; fm < 2; fm++) {
                    MMA16816(acc[fm][2 * g],     al[fm], rh[0], rh[2]);
                    MMA16816(acc[fm][2 * g + 1], al[fm], rh[1], rh[3]);
                }
            }
        }
        if (t + 2 < T)
            issue_tile<K, NT>(sb + (uint32_t)((t + 2) % 3) * STAGE, t + 2, bm, bn, Ah, Al, Bh, Bl, tid);
        asm volatile("cp.async.commit_group;" ::: "memory");
    }

    const int crow = lane >> 2, ccol = (lane & 3) * 2;
#pragma unroll
    for (int fm = 0; fm < 2; fm++)
#pragma unroll
        for (int fn = 0; fn < WNF; fn++) {
            int m = bm + wm * 32 + fm * 16 + crow;
            int n = bn + wn * WSPAN + fn * 8 + ccol;
            *(float2*)&C[(size_t)m * NS + n]       = make_float2(acc[fm][fn][0], acc[fm][fn][1]);
            *(float2*)&C[(size_t)(m + 8) * NS + n] = make_float2(acc[fm][fn][2], acc[fm][fn][3]);
        }
}

// ======================= depthwise causal conv (K=4) + SiLU =======================
__global__ void conv_silu_kernel(const float* __restrict__ conv_w,
                                 const float* __restrict__ conv_b) {
    int idx = blockIdx.x * blockDim.x + threadIdx.x;
    if (idx >= SEQ * CONV_DIM) return;
    int s = idx / CONV_DIM;
    int c = idx - s * CONV_DIM;
    float w0 = conv_w[c * 4 + 0], w1 = conv_w[c * 4 + 1];
    float w2 = conv_w[c * 4 + 2], w3 = conv_w[c * 4 + 3];
    const float* col = g_proj + INTER + c;
    float acc = conv_b[c];
    if (s >= 3) acc = fmaf(col[(size_t)(s - 3) * PROJ_DIM], w0, acc);
    if (s >= 2) acc = fmaf(col[(size_t)(s - 2) * PROJ_DIM], w1, acc);
    if (s >= 1) acc = fmaf(col[(size_t)(s - 1) * PROJ_DIM], w2, acc);
    acc = fmaf(col[(size_t)s * PROJ_DIM], w3, acc);
    float sig = 1.f / (1.f + __expf(-acc));
    g_conv[idx] = acc * sig;
}

// ======================= dt = softplus(dt_raw + dt_bias) =======================
__global__ void dt_kernel(const float* __restrict__ dt_bias) {
    int idx = blockIdx.x * blockDim.x + threadIdx.x;
    int h = idx & 63;
    int s = idx >> 6;
    float v = g_proj[(size_t)s * PROJ_DIM + (INTER + CONV_DIM) + h] + dt_bias[h];
    g_dt[idx] = (v > 20.f) ? v : log1pf(__expf(v));
}

// ======================= per-chunk cumsum(dt*A): warp scan per (c,h) =======================
__global__ void acum_kernel(const float* __restrict__ A_log) {
    int wg = blockIdx.x * 8 + (threadIdx.x >> 5);
    int lane = threadIdx.x & 31;
    int c = wg >> 6, h = wg & 63;
    float A = -__expf(A_log[h]);
    const float* dtp = g_dt + ((size_t)c * CHUNK) * NH + h;
    float v[8];
    float run = 0.f;
#pragma unroll
    for (int j = 0; j < 8; j++) {
        v[j] = dtp[(size_t)(lane * 8 + j) * NH] * A;
        run += v[j];
    }
    float s = run;
#pragma unroll
    for (int o = 1; o < 32; o <<= 1) {
        float t = __shfl_up_sync(0xffffffffu, s, o);
        if (lane >= o) s += t;
    }
    float acc = s - run;
    float* acp = g_acum + ((size_t)c * CHUNK) * NH + h;
#pragma unroll
    for (int j = 0; j < 8; j++) {
        acc += v[j];
        acp[(size_t)(lane * 8 + j) * NH] = acc;
    }
}

// ======================= CB[c][t][s] = C_t . B_s (shared over heads), s<=t tiles only =======================
__global__ __launch_bounds__(256) void cb_kernel() {
    int st = blockIdx.x, tt = blockIdx.y, c = blockIdx.z;
    if (st > tt) return;
    __shared__ float Cs[32][68];
    __shared__ float Bs2[32][68];
    const int tid = threadIdx.x;
    const int tx = tid & 15, ty = tid >> 4;
    float acc[4][4] = {};
    for (int n0 = 0; n0 < DS; n0 += 32) {
        __syncthreads();
        for (int e = tid; e < 64 * 32; e += 256) {
            int r = e >> 5, kk = e & 31;
            Cs[kk][r]  = g_conv[(size_t)(c * CHUNK + tt * 64 + r) * CONV_DIM + INTER + DS + n0 + kk];
            Bs2[kk][r] = g_conv[(size_t)(c * CHUNK + st * 64 + r) * CONV_DIM + INTER + n0 + kk];
        }
        __syncthreads();
#pragma unroll
        for (int k = 0; k < 32; k++) {
            float4 a = *(const float4*)&Cs[k][ty * 4];
            float4 b = *(const float4*)&Bs2[k][tx * 4];
            float av[4] = {a.x, a.y, a.z, a.w};
            float bv[4] = {b.x, b.y, b.z, b.w};
#pragma unroll
            for (int i = 0; i < 4; i++)
#pragma unroll
                for (int j = 0; j < 4; j++)
                    acc[i][j] = fmaf(av[i], bv[j], acc[i][j]);
        }
    }
#pragma unroll
    for (int i = 0; i < 4; i++)
        *(float4*)&g_cb[(size_t)c * CHUNK * CHUNK + (size_t)(tt * 64 + ty * 4 + i) * CHUNK + st * 64 + tx * 4] =
            make_float4(acc[i][0], acc[i][1], acc[i][2], acc[i][3]);
}

// ======================= chunk end states: states[c][h][p][n] =======================
__global__ __launch_bounds__(256) void states_kernel() {
    int h = blockIdx.x, c = blockIdx.y;
    __shared__ float Bt[32][DS];
    __shared__ float Xt[32][DH];
    __shared__ float wv[32];
    const int tid = threadIdx.x;
    const int p = tid >> 2, ng = tid & 3;
    float acc[32];
#pragma unroll
    for (int j = 0; j < 32; j++) acc[j] = 0.f;
    float Aend = g_acum[(size_t)(c * CHUNK + CHUNK - 1) * NH + h];
    for (int lt = 0; lt < 8; lt++) {
        __syncthreads();
        for (int e = tid; e < 32 * DS; e += 256) {
            int r = e >> 7, n = e & 127;
            Bt[r][n] = g_conv[(size_t)(c * CHUNK + lt * 32 + r) * CONV_DIM + INTER + n];
        }
        for (int e = tid; e < 32 * DH; e += 256) {
            int r = e >> 6, pp = e & 63;
            Xt[r][pp] = g_conv[(size_t)(c * CHUNK + lt * 32 + r) * CONV_DIM + h * DH + pp];
        }
        if (tid < 32) {
            int l = lt * 32 + tid;
            float ac = g_acum[(size_t)(c * CHUNK + l) * NH + h];
            wv[tid] = __expf(Aend - ac) * g_dt[(size_t)(c * CHUNK + l) * NH + h];
        }
        __syncthreads();
#pragma unroll 4
        for (int ls = 0; ls < 32; ls++) {
            float xv = Xt[ls][p] * wv[ls];
            const float* br = &Bt[ls][ng * 32];
#pragma unroll
            for (int j = 0; j < 32; j += 4) {
                float4 b4 = *(const float4*)(br + j);
                acc[j + 0] = fmaf(xv, b4.x, acc[j + 0]);
                acc[j + 1] = fmaf(xv, b4.y, acc[j + 1]);
                acc[j + 2] = fmaf(xv, b4.z, acc[j + 2]);
                acc[j + 3] = fmaf(xv, b4.w, acc[j + 3]);
            }
        }
    }
    float* dst = &g_states[(((size_t)c * NH + h) * DH + p) * DS + ng * 32];
#pragma unroll
    for (int j = 0; j < 32; j += 4)
        *(float4*)(dst + j) = make_float4(acc[j], acc[j + 1], acc[j + 2], acc[j + 3]);
}

// ======================= inter-chunk carry scan =======================
__global__ void carry_kernel() {
    int h = blockIdx.x;
    int tid = threadIdx.x;
    float carry[32];
#pragma unroll
    for (int j = 0; j < 32; j++) carry[j] = 0.f;
    for (int c = 0; c < NCH; c++) {
        float dec = __expf(g_acum[(size_t)(c * CHUNK + CHUNK - 1) * NH + h]);
        size_t off = ((size_t)c * NH + h) * DH * DS + (size_t)tid * 32;
#pragma unroll
        for (int j = 0; j < 32; j += 4) {
            float4 st = *(const float4*)&g_states[off + j];
            *(float4*)&g_prev[off + j] = make_float4(carry[j], carry[j + 1], carry[j + 2], carry[j + 3]);
            carry[j + 0] = fmaf(carry[j + 0], dec, st.x);
            carry[j + 1] = fmaf(carry[j + 1], dec, st.y);
            carry[j + 2] = fmaf(carry[j + 2], dec, st.z);
            carry[j + 3] = fmaf(carry[j + 3], dec, st.w);
        }
    }
}

// ======================= Y = intra + inter + D skip =======================
__global__ __launch_bounds__(256) void y_kernel(const float* __restrict__ Dp) {
    const int tt = blockIdx.x;
    const int h  = blockIdx.y;
    const int c  = blockIdx.z;
    __shared__ float sM[64][68];
    __shared__ float sX[64][68];
    __shared__ float sAcT[64], sAcS[64], sDt[64], sEt[64], sEs[64];
    const int tid = threadIdx.x;
    const int tx = tid & 15, ty = tid >> 4;

    if (tid < 64)
        sAcT[tid] = g_acum[(size_t)(c * CHUNK + tt * 64 + tid) * NH + h];

    float acc[4][4] = {};

    for (int n0 = 0; n0 < DS; n0 += 32) {
        __syncthreads();
        for (int e = tid; e < 64 * 32; e += 256) {
            int r = e >> 5, kk = e & 31;
            sM[kk][r] = g_conv[(size_t)(c * CHUNK + tt * 64 + r) * CONV_DIM + INTER + DS + n0 + kk];
            sX[kk][r] = g_prev[(((size_t)c * NH + h) * DH + r) * DS + n0 + kk];
        }
        __syncthreads();
#pragma unroll
        for (int k = 0; k < 32; k++) {
            float4 a = *(const float4*)&sM[k][ty * 4];
            float4 b = *(const float4*)&sX[k][tx * 4];
            float av[4] = {a.x, a.y, a.z, a.w};
            float bv[4] = {b.x, b.y, b.z, b.w};
#pragma unroll
            for (int i = 0; i < 4; i++)
#pragma unroll
                for (int j = 0; j < 4; j++)
                    acc[i][j] = fmaf(av[i], bv[j], acc[i][j]);
        }
    }
#pragma unroll
    for (int i = 0; i < 4; i++) {
        float e = __expf(sAcT[ty * 4 + i]);
#pragma unroll
        for (int j = 0; j < 4; j++) acc[i][j] *= e;
    }

    for (int st = 0; st <= tt; st++) {
        __syncthreads();
        if (tid < 64) {
            sAcS[tid] = g_acum[(size_t)(c * CHUNK + st * 64 + tid) * NH + h];
            sDt[tid]  = g_dt  [(size_t)(c * CHUNK + st * 64 + tid) * NH + h];
        }
        __syncthreads();
        if (st < tt && tid < 64) {
            float ref = sAcS[63];
            sEt[tid] = __expf(sAcT[tid] - ref);
            sEs[tid] = __expf(ref - sAcS[tid]) * sDt[tid];
        }
        __syncthreads();
        for (int e = tid; e < 64 * 64; e += 256) {
            int t = e >> 6, s = e & 63;
            float cb = g_cb[(size_t)c * CHUNK * CHUNK + (size_t)(tt * 64 + t) * CHUNK + st * 64 + s];
            float m;
            if (st < tt) m = cb * sEt[t] * sEs[s];
            else         m = (s <= t) ? cb * __expf(sAcT[t] - sAcS[s]) * sDt[s] : 0.f;
            sM[s][t] = m;
        }
        for (int e = tid; e < 64 * 64; e += 256) {
            int s = e >> 6, pp = e & 63;
            sX[s][pp] = g_conv[(size_t)(c * CHUNK + st * 64 + s) * CONV_DIM + h * DH + pp];
        }
        __syncthreads();
#pragma unroll 8
        for (int s = 0; s < 64; s++) {
            float4 a = *(const float4*)&sM[s][ty * 4];
            float4 b = *(const float4*)&sX[s][tx * 4];
            float av[4] = {a.x, a.y, a.z, a.w};
            float bv[4] = {b.x, b.y, b.z, b.w};
#pragma unroll
            for (int i = 0; i < 4; i++)
#pragma unroll
                for (int j = 0; j < 4; j++)
                    acc[i][j] = fmaf(av[i], bv[j], acc[i][j]);
        }
    }

    float dv = Dp[h];
#pragma unroll
    for (int i = 0; i < 4; i++)
#pragma unroll
        for (int j = 0; j < 4; j++)
            acc[i][j] = fmaf(dv, sX[ty * 4 + i][tx * 4 + j], acc[i][j]);

#pragma unroll
    for (int i = 0; i < 4; i++)
        *(float4*)&g_y[(size_t)(c * CHUNK + tt * 64 + ty * 4 + i) * INTER + h * DH + tx * 4] =
            make_float4(acc[i][0], acc[i][1], acc[i][2], acc[i][3]);
}

// ======================= gated RMSNorm -> bf16 split output =======================
__global__ __launch_bounds__(256) void norm_kernel(const float* __restrict__ norm_w) {
    int s = blockIdx.x;
    int tid = threadIdx.x;
    float v[16];
    float ss = 0.f;
#pragma unroll
    for (int q = 0; q < 4; q++) {
        int i4 = tid + q * 256;
        float4 y4 = *(const float4*)&g_y[(size_t)s * INTER + (size_t)i4 * 4];
        float4 g4 = *(const float4*)&g_proj[(size_t)s * PROJ_DIM + (size_t)i4 * 4];
        float t0 = y4.x * (g4.x / (1.f + __expf(-g4.x)));
        float t1 = y4.y * (g4.y / (1.f + __expf(-g4.y)));
        float t2 = y4.z * (g4.z / (1.f + __expf(-g4.z)));
        float t3 = y4.w * (g4.w / (1.f + __expf(-g4.w)));
        v[q * 4 + 0] = t0; v[q * 4 + 1] = t1; v[q * 4 + 2] = t2; v[q * 4 + 3] = t3;
        ss += t0 * t0 + t1 * t1 + t2 * t2 + t3 * t3;
    }
#pragma unroll
    for (int o = 16; o > 0; o >>= 1) ss += __shfl_xor_sync(0xffffffffu, ss, o);
    __shared__ float red[8];
    if ((tid & 31) == 0) red[tid >> 5] = ss;
    __syncthreads();
    float tot = red[0] + red[1] + red[2] + red[3] + red[4] + red[5] + red[6] + red[7];
    float scale = rsqrtf(tot * (1.f / INTER) + 1e-5f);
#pragma unroll
    for (int q = 0; q < 4; q++) {
        int i4 = tid + q * 256;
        float4 w4 = *(const float4*)&norm_w[(size_t)i4 * 4];
        float o0 = v[q * 4 + 0] * scale * w4.x;
        float o1 = v[q * 4 + 1] * scale * w4.y;
        float o2 = v[q * 4 + 2] * scale * w4.z;
        float o3 = v[q * 4 + 3] * scale * w4.w;
        __nv_bfloat16 h0 = __float2bfloat16(o0), h1 = __float2bfloat16(o1);
        __nv_bfloat16 h2 = __float2bfloat16(o2), h3 = __float2bfloat16(o3);
        __nv_bfloat16 l0 = __float2bfloat16(o0 - __bfloat162float(h0));
        __nv_bfloat16 l1 = __float2bfloat16(o1 - __bfloat162float(h1));
        __nv_bfloat16 l2 = __float2bfloat16(o2 - __bfloat162float(h2));
        __nv_bfloat16 l3 = __float2bfloat16(o3 - __bfloat162float(h3));
        size_t base = (size_t)s * INTER + (size_t)i4 * 4;
        *(__nv_bfloat162*)(g_yh + base)     = __nv_bfloat162(h0, h1);
        *(__nv_bfloat162*)(g_yh + base + 2) = __nv_bfloat162(h2, h3);
        *(__nv_bfloat162*)(g_yl + base)     = __nv_bfloat162(l0, l1);
        *(__nv_bfloat162*)(g_yl + base + 2) = __nv_bfloat162(l2, l3);
    }
}

// ======================= launch =======================
extern "C" void kernel_launch(void* const* d_in, const int* in_sizes, int n_in,
                              void* d_out, int out_size) {
    (void)in_sizes; (void)n_in; (void)out_size;
    const float* x       = (const float*)d_in[0];
    const float* W_in    = (const float*)d_in[1];
    const float* conv_w  = (const float*)d_in[2];
    const float* conv_b  = (const float*)d_in[3];
    const float* dt_bias = (const float*)d_in[4];
    const float* A_log   = (const float*)d_in[5];
    const float* Dp      = (const float*)d_in[6];
    const float* norm_w  = (const float*)d_in[7];
    const float* W_out   = (const float*)d_in[8];
    float* out = (float*)d_out;

    // stage = 2*A(10240) + 2*B(NT*80): NT=256 -> 61440; NT=64 -> 30720. 3 stages.
    const int SM256 = 3 * (2 * 128 * PITCH * 2 + 2 * 256 * PITCH * 2); // 184320
    const int SM64  = 3 * (2 * 128 * PITCH * 2 + 2 * 64 * PITCH * 2);  // 92160
    cudaFuncSetAttribute(gemm_mma_kernel<HIDDEN, PROJ_DIM, 256>,
                         cudaFuncAttributeMaxDynamicSharedMemorySize, SM256);
    cudaFuncSetAttribute(gemm_mma_kernel<HIDDEN, PROJ_DIM, 64>,
                         cudaFuncAttributeMaxDynamicSharedMemorySize, SM64);
    cudaFuncSetAttribute(gemm_mma_kernel<INTER, HIDDEN, 256>,
                         cudaFuncAttributeMaxDynamicSharedMemorySize, SM256);

    __nv_bfloat16 *xh, *xl, *wih, *wil, *yh, *yl, *woh, *wol;
    cudaGetSymbolAddress((void**)&xh,  g_xh);  cudaGetSymbolAddress((void**)&xl,  g_xl);
    cudaGetSymbolAddress((void**)&wih, g_wih); cudaGetSymbolAddress((void**)&wil, g_wil);
    cudaGetSymbolAddress((void**)&yh,  g_yh);  cudaGetSymbolAddress((void**)&yl,  g_yl);
    cudaGetSymbolAddress((void**)&woh, g_woh); cudaGetSymbolAddress((void**)&wol, g_wol);
    float* proj; cudaGetSymbolAddress((void**)&proj, g_proj);

    split_kernel<<<(SEQ * HIDDEN / 4 + 255) / 256, 256>>>(x, xh, xl, SEQ * HIDDEN);
    split_kernel<<<(PROJ_DIM * HIDDEN / 4 + 255) / 256, 256>>>(W_in, wih, wil, PROJ_DIM * HIDDEN);
    split_kernel<<<(HIDDEN * INTER / 4 + 255) / 256, 256>>>(W_out, woh, wol, HIDDEN * INTER);

    gemm_mma_kernel<HIDDEN, PROJ_DIM, 256><<<dim3(33, 16), 512, SM256>>>(xh, xl, wih, wil, proj, 0);
    gemm_mma_kernel<HIDDEN, PROJ_DIM, 64><<<dim3(1, 16), 512, SM64>>>(xh, xl, wih, wil, proj, 8448);

    conv_silu_kernel<<<(SEQ * CONV_DIM + 255) / 256, 256>>>(conv_w, conv_b);
    dt_kernel<<<(SEQ * NH) / 256, 256>>>(dt_bias);
    acum_kernel<<<64, 256>>>(A_log);
    cb_kernel<<<dim3(4, 4, NCH), 256>>>();
    states_kernel<<<dim3(NH, NCH), 256>>>();
    carry_kernel<<<NH, 256>>>();
    y_kernel<<<dim3(4, NH, NCH), 256>>>(Dp);
    norm_kernel<<<SEQ, 256>>>(norm_w);

    gemm_mma_kernel<INTER, HIDDEN, 256><<<dim3(8, 16), 512, SM256>>>(yh, yl, woh, wol, out, 0);
}

// round 14
// speedup vs baseline: 2.1214x; 1.2104x over previous
#include <cuda_runtime.h>
#include <cuda_fp16.h>
#include <stdint.h>
#include <math.h>

#define SEQ 2048
#define HIDDEN 2048
#define INTER 4096
#define NH 64
#define DH 64
#define DS 128
#define CHUNK 256
#define NCH 8
#define CONV_DIM 4352
#define PROJ_DIM 8512

// -------- scratch (device globals; no allocation allowed) --------
__device__ float g_proj[SEQ * PROJ_DIM];
__device__ float g_conv[SEQ * CONV_DIM];
__device__ float g_dt[SEQ * NH];
__device__ float g_acum[SEQ * NH];
__device__ float g_cb[NCH * CHUNK * CHUNK];
__device__ float g_states[NCH * NH * DH * DS];
__device__ float g_prev[NCH * NH * DH * DS];
__device__ float g_y[SEQ * INTER];

// fp16 split operands for tensor-core GEMMs (A gets hi+lo, B gets hi only)
__device__ __half g_xh[SEQ * HIDDEN],    g_xl[SEQ * HIDDEN];
__device__ __half g_wih[PROJ_DIM * HIDDEN];
__device__ __half g_yh[SEQ * INTER],     g_yl[SEQ * INTER];
__device__ __half g_woh[HIDDEN * INTER];

// ======================= helpers =======================
__device__ __forceinline__ uint32_t smem_u32(const void* p) {
    uint32_t a;
    asm("{ .reg .u64 t; cvta.to.shared.u64 t, %1; cvt.u32.u64 %0, t; }" : "=r"(a) : "l"(p));
    return a;
}

#define LDSM4(r, a) \
    asm volatile("ldmatrix.sync.aligned.m8n8.x4.shared.b16 {%0,%1,%2,%3}, [%4];" \
        : "=r"((r)[0]), "=r"((r)[1]), "=r"((r)[2]), "=r"((r)[3]) : "r"(a))

#define MMA16816(c, a, b0, b1) \
    asm volatile("mma.sync.aligned.m16n8k16.row.col.f32.f16.f16.f32 " \
        "{%0,%1,%2,%3}, {%4,%5,%6,%7}, {%8,%9}, {%0,%1,%2,%3};" \
        : "+f"((c)[0]), "+f"((c)[1]), "+f"((c)[2]), "+f"((c)[3]) \
        : "r"((a)[0]), "r"((a)[1]), "r"((a)[2]), "r"((a)[3]), "r"(b0), "r"(b1))

__device__ __forceinline__ void cp16(uint32_t dst, const void* src) {
    unsigned long long g = (unsigned long long)__cvta_generic_to_global(src);
    asm volatile("cp.async.cg.shared.global [%0], [%1], 16;" :: "r"(dst), "l"(g));
}

// ======================= fp32 -> fp16 splits =======================
__global__ void split2_kernel(const float* __restrict__ in, __half* __restrict__ hi,
                              __half* __restrict__ lo, int n) {
    int i = (blockIdx.x * blockDim.x + threadIdx.x) * 4;
    if (i >= n) return;
    float4 v = *(const float4*)(in + i);
    __half h0 = __float2half_rn(v.x), h1 = __float2half_rn(v.y);
    __half h2 = __float2half_rn(v.z), h3 = __float2half_rn(v.w);
    __half l0 = __float2half_rn(v.x - __half2float(h0));
    __half l1 = __float2half_rn(v.y - __half2float(h1));
    __half l2 = __float2half_rn(v.z - __half2float(h2));
    __half l3 = __float2half_rn(v.w - __half2float(h3));
    *(__half2*)(hi + i)     = __half2(h0, h1);
    *(__half2*)(hi + i + 2) = __half2(h2, h3);
    *(__half2*)(lo + i)     = __half2(l0, l1);
    *(__half2*)(lo + i + 2) = __half2(l2, l3);
}

__global__ void split1_kernel(const float* __restrict__ in, __half* __restrict__ hi, int n) {
    int i = (blockIdx.x * blockDim.x + threadIdx.x) * 4;
    if (i >= n) return;
    float4 v = *(const float4*)(in + i);
    *(__half2*)(hi + i)     = __half2(__float2half_rn(v.x), __float2half_rn(v.y));
    *(__half2*)(hi + i + 2) = __half2(__float2half_rn(v.z), __float2half_rn(v.w));
}

// ======================= mma.sync GEMM: C[M, slice] = A[M,K] * B[N,K]^T =======================
// A = Ah + Al (fp16 pair, exact to 2^-22); B = Bh (fp16). 2 MMAs per logical product.
// CTA 128 x NT (NT=256 main / 64 tail), 512 threads (warps 4x4), 4-stage cp.async.
#define PITCH 40

template<int K, int NT>
__device__ __forceinline__ void issue_tile(uint32_t st, int t, int bm, int bn,
        const __half* __restrict__ Ah, const __half* __restrict__ Al,
        const __half* __restrict__ Bh, int tid) {
    constexpr int ABYTES = 128 * PITCH * 2;
    const int kt = t * 32;
    {   // A: 128 rows x 4 chunks = 512 chunks (one per thread), hi + lo
        int r = tid >> 2, q = tid & 3;
        size_t src = (size_t)(bm + r) * K + kt + q * 8;
        uint32_t d = st + (uint32_t)(r * PITCH + q * 8) * 2;
        cp16(d, Ah + src);
        cp16(d + ABYTES, Al + src);
    }
    constexpr int BCH = NT * 4;
#pragma unroll
    for (int i = 0; i < (BCH + 511) / 512; i++) {
        int cid = tid + i * 512;
        if ((BCH % 512 == 0) || cid < BCH) {
            int r = cid >> 2, q = cid & 3;
            size_t src = (size_t)(bn + r) * K + kt + q * 8;
            cp16(st + 2 * ABYTES + (uint32_t)(r * PITCH + q * 8) * 2, Bh + src);
        }
    }
}

template<int K, int NS, int NT>
__global__ __launch_bounds__(512, 1) void gemm_mma_kernel(
        const __half* __restrict__ Ah, const __half* __restrict__ Al,
        const __half* __restrict__ Bh,
        float* __restrict__ C, int n0) {
    extern __shared__ char smem[];
    constexpr int ABYTES = 128 * PITCH * 2;
    constexpr int BBYTES = NT * PITCH * 2;
    constexpr int STAGE = 2 * ABYTES + BBYTES;
    constexpr int T = K / 32;
    constexpr int WNF = NT / 32;        // n8 frags per warp (4 n-warps)
    constexpr int WSPAN = NT / 4;       // cols per warp

    const int tid = threadIdx.x;
    const int lane = tid & 31, wid = tid >> 5;
    const int wm = wid & 3, wn = wid >> 2;
    const int bm = blockIdx.y * 128;
    const int bn = n0 + blockIdx.x * NT;
    const uint32_t sb = smem_u32(smem);

    float acc[2][WNF][4];
#pragma unroll
    for (int i = 0; i < 2; i++)
#pragma unroll
        for (int j = 0; j < WNF; j++)
#pragma unroll
            for (int q = 0; q < 4; q++) acc[i][j][q] = 0.f;

    issue_tile<K, NT>(sb,             0, bm, bn, Ah, Al, Bh, tid);
    asm volatile("cp.async.commit_group;" ::: "memory");
    issue_tile<K, NT>(sb + STAGE,     1, bm, bn, Ah, Al, Bh, tid);
    asm volatile("cp.async.commit_group;" ::: "memory");
    issue_tile<K, NT>(sb + 2 * STAGE, 2, bm, bn, Ah, Al, Bh, tid);
    asm volatile("cp.async.commit_group;" ::: "memory");

    const int lrow = lane & 15;
    const int lcol = (lane >> 4) * 8;
    const uint32_t aoff = (uint32_t)((wm * 32 + lrow) * PITCH + lcol) * 2;
    const uint32_t boff = 2 * ABYTES + (uint32_t)((wn * WSPAN + lrow) * PITCH + lcol) * 2;

    for (int t = 0; t < T; t++) {
        asm volatile("cp.async.wait_group 2;" ::: "memory");
        __syncthreads();
        const uint32_t stg = sb + (uint32_t)(t & 3) * STAGE;
#pragma unroll
        for (int kk = 0; kk < 32; kk += 16) {
            uint32_t ah[2][4], al[2][4];
#pragma unroll
            for (int fm = 0; fm < 2; fm++) {
                uint32_t ad = stg + aoff + (uint32_t)(fm * 16 * PITCH + kk) * 2;
                LDSM4(ah[fm], ad);
                LDSM4(al[fm], ad + ABYTES);
            }
#pragma unroll
            for (int g = 0; g < WNF / 2; g++) {
                uint32_t bd = stg + boff + (uint32_t)(g * 16 * PITCH + kk) * 2;
                uint32_t rh[4];
                LDSM4(rh, bd);
                // product 1: ah * bh
#pragma unroll
                for (int fm = 0; fm < 2; fm++) {
                    MMA16816(acc[fm][2 * g],     ah[fm], rh[0], rh[2]);
                    MMA16816(acc[fm][2 * g + 1], ah[fm], rh[1], rh[3]);
                }
                // product 2: al * bh
#pragma unroll
                for (int fm = 0; fm < 2; fm++) {
                    MMA16816(acc[fm][2 * g],     al[fm], rh[0], rh[2]);
                    MMA16816(acc[fm][2 * g + 1], al[fm], rh[1], rh[3]);
                }
            }
        }
        if (t + 3 < T)
            issue_tile<K, NT>(sb + (uint32_t)((t + 3) & 3) * STAGE, t + 3, bm, bn, Ah, Al, Bh, tid);
        asm volatile("cp.async.commit_group;" ::: "memory");
    }

    const int crow = lane >> 2, ccol = (lane & 3) * 2;
#pragma unroll
    for (int fm = 0; fm < 2; fm++)
#pragma unroll
        for (int fn = 0; fn < WNF; fn++) {
            int m = bm + wm * 32 + fm * 16 + crow;
            int n = bn + wn * WSPAN + fn * 8 + ccol;
            *(float2*)&C[(size_t)m * NS + n]       = make_float2(acc[fm][fn][0], acc[fm][fn][1]);
            *(float2*)&C[(size_t)(m + 8) * NS + n] = make_float2(acc[fm][fn][2], acc[fm][fn][3]);
        }
}

// ======================= depthwise causal conv (K=4) + SiLU =======================
__global__ void conv_silu_kernel(const float* __restrict__ conv_w,
                                 const float* __restrict__ conv_b) {
    int idx = blockIdx.x * blockDim.x + threadIdx.x;
    if (idx >= SEQ * CONV_DIM) return;
    int s = idx / CONV_DIM;
    int c = idx - s * CONV_DIM;
    float w0 = conv_w[c * 4 + 0], w1 = conv_w[c * 4 + 1];
    float w2 = conv_w[c * 4 + 2], w3 = conv_w[c * 4 + 3];
    const float* col = g_proj + INTER + c;
    float acc = conv_b[c];
    if (s >= 3) acc = fmaf(col[(size_t)(s - 3) * PROJ_DIM], w0, acc);
    if (s >= 2) acc = fmaf(col[(size_t)(s - 2) * PROJ_DIM], w1, acc);
    if (s >= 1) acc = fmaf(col[(size_t)(s - 1) * PROJ_DIM], w2, acc);
    acc = fmaf(col[(size_t)s * PROJ_DIM], w3, acc);
    float sig = 1.f / (1.f + __expf(-acc));
    g_conv[idx] = acc * sig;
}

// ======================= dt = softplus(dt_raw + dt_bias) =======================
__global__ void dt_kernel(const float* __restrict__ dt_bias) {
    int idx = blockIdx.x * blockDim.x + threadIdx.x;
    int h = idx & 63;
    int s = idx >> 6;
    float v = g_proj[(size_t)s * PROJ_DIM + (INTER + CONV_DIM) + h] + dt_bias[h];
    g_dt[idx] = (v > 20.f) ? v : log1pf(__expf(v));
}

// ======================= per-chunk cumsum(dt*A): warp scan per (c,h) =======================
__global__ void acum_kernel(const float* __restrict__ A_log) {
    int wg = blockIdx.x * 8 + (threadIdx.x >> 5);
    int lane = threadIdx.x & 31;
    int c = wg >> 6, h = wg & 63;
    float A = -__expf(A_log[h]);
    const float* dtp = g_dt + ((size_t)c * CHUNK) * NH + h;
    float v[8];
    float run = 0.f;
#pragma unroll
    for (int j = 0; j < 8; j++) {
        v[j] = dtp[(size_t)(lane * 8 + j) * NH] * A;
        run += v[j];
    }
    float s = run;
#pragma unroll
    for (int o = 1; o < 32; o <<= 1) {
        float t = __shfl_up_sync(0xffffffffu, s, o);
        if (lane >= o) s += t;
    }
    float acc = s - run;
    float* acp = g_acum + ((size_t)c * CHUNK) * NH + h;
#pragma unroll
    for (int j = 0; j < 8; j++) {
        acc += v[j];
        acp[(size_t)(lane * 8 + j) * NH] = acc;
    }
}

// ======================= CB[c][t][s] = C_t . B_s (shared over heads), s<=t tiles only =======================
__global__ __launch_bounds__(256) void cb_kernel() {
    int st = blockIdx.x, tt = blockIdx.y, c = blockIdx.z;
    if (st > tt) return;
    __shared__ float Cs[32][68];
    __shared__ float Bs2[32][68];
    const int tid = threadIdx.x;
    const int tx = tid & 15, ty = tid >> 4;
    float acc[4][4] = {};
    for (int n0 = 0; n0 < DS; n0 += 32) {
        __syncthreads();
        for (int e = tid; e < 64 * 32; e += 256) {
            int r = e >> 5, kk = e & 31;
            Cs[kk][r]  = g_conv[(size_t)(c * CHUNK + tt * 64 + r) * CONV_DIM + INTER + DS + n0 + kk];
            Bs2[kk][r] = g_conv[(size_t)(c * CHUNK + st * 64 + r) * CONV_DIM + INTER + n0 + kk];
        }
        __syncthreads();
#pragma unroll
        for (int k = 0; k < 32; k++) {
            float4 a = *(const float4*)&Cs[k][ty * 4];
            float4 b = *(const float4*)&Bs2[k][tx * 4];
            float av[4] = {a.x, a.y, a.z, a.w};
            float bv[4] = {b.x, b.y, b.z, b.w};
#pragma unroll
            for (int i = 0; i < 4; i++)
#pragma unroll
                for (int j = 0; j < 4; j++)
                    acc[i][j] = fmaf(av[i], bv[j], acc[i][j]);
        }
    }
#pragma unroll
    for (int i = 0; i < 4; i++)
        *(float4*)&g_cb[(size_t)c * CHUNK * CHUNK + (size_t)(tt * 64 + ty * 4 + i) * CHUNK + st * 64 + tx * 4] =
            make_float4(acc[i][0], acc[i][1], acc[i][2], acc[i][3]);
}

// ======================= chunk end states: states[c][h][p][n] =======================
__global__ __launch_bounds__(256) void states_kernel() {
    int h = blockIdx.x, c = blockIdx.y;
    __shared__ float Bt[32][DS];
    __shared__ float Xt[32][DH];
    __shared__ float wv[32];
    const int tid = threadIdx.x;
    const int p = tid >> 2, ng = tid & 3;
    float acc[32];
#pragma unroll
    for (int j = 0; j < 32; j++) acc[j] = 0.f;
    float Aend = g_acum[(size_t)(c * CHUNK + CHUNK - 1) * NH + h];
    for (int lt = 0; lt < 8; lt++) {
        __syncthreads();
        for (int e = tid; e < 32 * DS; e += 256) {
            int r = e >> 7, n = e & 127;
            Bt[r][n] = g_conv[(size_t)(c * CHUNK + lt * 32 + r) * CONV_DIM + INTER + n];
        }
        for (int e = tid; e < 32 * DH; e += 256) {
            int r = e >> 6, pp = e & 63;
            Xt[r][pp] = g_conv[(size_t)(c * CHUNK + lt * 32 + r) * CONV_DIM + h * DH + pp];
        }
        if (tid < 32) {
            int l = lt * 32 + tid;
            float ac = g_acum[(size_t)(c * CHUNK + l) * NH + h];
            wv[tid] = __expf(Aend - ac) * g_dt[(size_t)(c * CHUNK + l) * NH + h];
        }
        __syncthreads();
#pragma unroll 4
        for (int ls = 0; ls < 32; ls++) {
            float xv = Xt[ls][p] * wv[ls];
            const float* br = &Bt[ls][ng * 32];
#pragma unroll
            for (int j = 0; j < 32; j += 4) {
                float4 b4 = *(const float4*)(br + j);
                acc[j + 0] = fmaf(xv, b4.x, acc[j + 0]);
                acc[j + 1] = fmaf(xv, b4.y, acc[j + 1]);
                acc[j + 2] = fmaf(xv, b4.z, acc[j + 2]);
                acc[j + 3] = fmaf(xv, b4.w, acc[j + 3]);
            }
        }
    }
    float* dst = &g_states[(((size_t)c * NH + h) * DH + p) * DS + ng * 32];
#pragma unroll
    for (int j = 0; j < 32; j += 4)
        *(float4*)(dst + j) = make_float4(acc[j], acc[j + 1], acc[j + 2], acc[j + 3]);
}

// ======================= inter-chunk carry scan =======================
__global__ void carry_kernel() {
    int h = blockIdx.x;
    int tid = threadIdx.x;
    float carry[32];
#pragma unroll
    for (int j = 0; j < 32; j++) carry[j] = 0.f;
    for (int c = 0; c < NCH; c++) {
        float dec = __expf(g_acum[(size_t)(c * CHUNK + CHUNK - 1) * NH + h]);
        size_t off = ((size_t)c * NH + h) * DH * DS + (size_t)tid * 32;
#pragma unroll
        for (int j = 0; j < 32; j += 4) {
            float4 st = *(const float4*)&g_states[off + j];
            *(float4*)&g_prev[off + j] = make_float4(carry[j], carry[j + 1], carry[j + 2], carry[j + 3]);
            carry[j + 0] = fmaf(carry[j + 0], dec, st.x);
            carry[j + 1] = fmaf(carry[j + 1], dec, st.y);
            carry[j + 2] = fmaf(carry[j + 2], dec, st.z);
            carry[j + 3] = fmaf(carry[j + 3], dec, st.w);
        }
    }
}

// ======================= Y = intra + inter + D skip =======================
__global__ __launch_bounds__(256) void y_kernel(const float* __restrict__ Dp) {
    const int tt = blockIdx.x;
    const int h  = blockIdx.y;
    const int c  = blockIdx.z;
    __shared__ float sM[64][68];
    __shared__ float sX[64][68];
    __shared__ float sAcT[64], sAcS[64], sDt[64], sEt[64], sEs[64];
    const int tid = threadIdx.x;
    const int tx = tid & 15, ty = tid >> 4;

    if (tid < 64)
        sAcT[tid] = g_acum[(size_t)(c * CHUNK + tt * 64 + tid) * NH + h];

    float acc[4][4] = {};

    for (int n0 = 0; n0 < DS; n0 += 32) {
        __syncthreads();
        for (int e = tid; e < 64 * 32; e += 256) {
            int r = e >> 5, kk = e & 31;
            sM[kk][r] = g_conv[(size_t)(c * CHUNK + tt * 64 + r) * CONV_DIM + INTER + DS + n0 + kk];
            sX[kk][r] = g_prev[(((size_t)c * NH + h) * DH + r) * DS + n0 + kk];
        }
        __syncthreads();
#pragma unroll
        for (int k = 0; k < 32; k++) {
            float4 a = *(const float4*)&sM[k][ty * 4];
            float4 b = *(const float4*)&sX[k][tx * 4];
            float av[4] = {a.x, a.y, a.z, a.w};
            float bv[4] = {b.x, b.y, b.z, b.w};
#pragma unroll
            for (int i = 0; i < 4; i++)
#pragma unroll
                for (int j = 0; j < 4; j++)
                    acc[i][j] = fmaf(av[i], bv[j], acc[i][j]);
        }
    }
#pragma unroll
    for (int i = 0; i < 4; i++) {
        float e = __expf(sAcT[ty * 4 + i]);
#pragma unroll
        for (int j = 0; j < 4; j++) acc[i][j] *= e;
    }

    for (int st = 0; st <= tt; st++) {
        __syncthreads();
        if (tid < 64) {
            sAcS[tid] = g_acum[(size_t)(c * CHUNK + st * 64 + tid) * NH + h];
            sDt[tid]  = g_dt  [(size_t)(c * CHUNK + st * 64 + tid) * NH + h];
        }
        __syncthreads();
        if (st < tt && tid < 64) {
            float ref = sAcS[63];
            sEt[tid] = __expf(sAcT[tid] - ref);
            sEs[tid] = __expf(ref - sAcS[tid]) * sDt[tid];
        }
        __syncthreads();
        for (int e = tid; e < 64 * 64; e += 256) {
            int t = e >> 6, s = e & 63;
            float cb = g_cb[(size_t)c * CHUNK * CHUNK + (size_t)(tt * 64 + t) * CHUNK + st * 64 + s];
            float m;
            if (st < tt) m = cb * sEt[t] * sEs[s];
            else         m = (s <= t) ? cb * __expf(sAcT[t] - sAcS[s]) * sDt[s] : 0.f;
            sM[s][t] = m;
        }
        for (int e = tid; e < 64 * 64; e += 256) {
            int s = e >> 6, pp = e & 63;
            sX[s][pp] = g_conv[(size_t)(c * CHUNK + st * 64 + s) * CONV_DIM + h * DH + pp];
        }
        __syncthreads();
#pragma unroll 8
        for (int s = 0; s < 64; s++) {
            float4 a = *(const float4*)&sM[s][ty * 4];
            float4 b = *(const float4*)&sX[s][tx * 4];
            float av[4] = {a.x, a.y, a.z, a.w};
            float bv[4] = {b.x, b.y, b.z, b.w};
#pragma unroll
            for (int i = 0; i < 4; i++)
#pragma unroll
                for (int j = 0; j < 4; j++)
                    acc[i][j] = fmaf(av[i], bv[j], acc[i][j]);
        }
    }

    float dv = Dp[h];
#pragma unroll
    for (int i = 0; i < 4; i++)
#pragma unroll
        for (int j = 0; j < 4; j++)
            acc[i][j] = fmaf(dv, sX[ty * 4 + i][tx * 4 + j], acc[i][j]);

#pragma unroll
    for (int i = 0; i < 4; i++)
        *(float4*)&g_y[(size_t)(c * CHUNK + tt * 64 + ty * 4 + i) * INTER + h * DH + tx * 4] =
            make_float4(acc[i][0], acc[i][1], acc[i][2], acc[i][3]);
}

// ======================= gated RMSNorm -> fp16 split output =======================
__global__ __launch_bounds__(256) void norm_kernel(const float* __restrict__ norm_w) {
    int s = blockIdx.x;
    int tid = threadIdx.x;
    float v[16];
    float ss = 0.f;
#pragma unroll
    for (int q = 0; q < 4; q++) {
        int i4 = tid + q * 256;
        float4 y4 = *(const float4*)&g_y[(size_t)s * INTER + (size_t)i4 * 4];
        float4 g4 = *(const float4*)&g_proj[(size_t)s * PROJ_DIM + (size_t)i4 * 4];
        float t0 = y4.x * (g4.x / (1.f + __expf(-g4.x)));
        float t1 = y4.y * (g4.y / (1.f + __expf(-g4.y)));
        float t2 = y4.z * (g4.z / (1.f + __expf(-g4.z)));
        float t3 = y4.w * (g4.w / (1.f + __expf(-g4.w)));
        v[q * 4 + 0] = t0; v[q * 4 + 1] = t1; v[q * 4 + 2] = t2; v[q * 4 + 3] = t3;
        ss += t0 * t0 + t1 * t1 + t2 * t2 + t3 * t3;
    }
#pragma unroll
    for (int o = 16; o > 0; o >>= 1) ss += __shfl_xor_sync(0xffffffffu, ss, o);
    __shared__ float red[8];
    if ((tid & 31) == 0) red[tid >> 5] = ss;
    __syncthreads();
    float tot = red[0] + red[1] + red[2] + red[3] + red[4] + red[5] + red[6] + red[7];
    float scale = rsqrtf(tot * (1.f / INTER) + 1e-5f);
#pragma unroll
    for (int q = 0; q < 4; q++) {
        int i4 = tid + q * 256;
        float4 w4 = *(const float4*)&norm_w[(size_t)i4 * 4];
        float o0 = v[q * 4 + 0] * scale * w4.x;
        float o1 = v[q * 4 + 1] * scale * w4.y;
        float o2 = v[q * 4 + 2] * scale * w4.z;
        float o3 = v[q * 4 + 3] * scale * w4.w;
        __half h0 = __float2half_rn(o0), h1 = __float2half_rn(o1);
        __half h2 = __float2half_rn(o2), h3 = __float2half_rn(o3);
        __half l0 = __float2half_rn(o0 - __half2float(h0));
        __half l1 = __float2half_rn(o1 - __half2float(h1));
        __half l2 = __float2half_rn(o2 - __half2float(h2));
        __half l3 = __float2half_rn(o3 - __half2float(h3));
        size_t base = (size_t)s * INTER + (size_t)i4 * 4;
        *(__half2*)(g_yh + base)     = __half2(h0, h1);
        *(__half2*)(g_yh + base + 2) = __half2(h2, h3);
        *(__half2*)(g_yl + base)     = __half2(l0, l1);
        *(__half2*)(g_yl + base + 2) = __half2(l2, l3);
    }
}

// ======================= launch =======================
extern "C" void kernel_launch(void* const* d_in, const int* in_sizes, int n_in,
                              void* d_out, int out_size) {
    (void)in_sizes; (void)n_in; (void)out_size;
    const float* x       = (const float*)d_in[0];
    const float* W_in    = (const float*)d_in[1];
    const float* conv_w  = (const float*)d_in[2];
    const float* conv_b  = (const float*)d_in[3];
    const float* dt_bias = (const float*)d_in[4];
    const float* A_log   = (const float*)d_in[5];
    const float* Dp      = (const float*)d_in[6];
    const float* norm_w  = (const float*)d_in[7];
    const float* W_out   = (const float*)d_in[8];
    float* out = (float*)d_out;

    // stage = 2*A(10240) + B(NT*80): NT=256 -> 40960; NT=64 -> 25600. 4 stages.
    const int SM256 = 4 * (2 * 128 * PITCH * 2 + 256 * PITCH * 2); // 163840
    const int SM64  = 4 * (2 * 128 * PITCH * 2 + 64 * PITCH * 2);  // 102400
    cudaFuncSetAttribute(gemm_mma_kernel<HIDDEN, PROJ_DIM, 256>,
                         cudaFuncAttributeMaxDynamicSharedMemorySize, SM256);
    cudaFuncSetAttribute(gemm_mma_kernel<HIDDEN, PROJ_DIM, 64>,
                         cudaFuncAttributeMaxDynamicSharedMemorySize, SM64);
    cudaFuncSetAttribute(gemm_mma_kernel<INTER, HIDDEN, 256>,
                         cudaFuncAttributeMaxDynamicSharedMemorySize, SM256);

    __half *xh, *xl, *wih, *yh, *yl, *woh;
    cudaGetSymbolAddress((void**)&xh,  g_xh);  cudaGetSymbolAddress((void**)&xl,  g_xl);
    cudaGetSymbolAddress((void**)&wih, g_wih);
    cudaGetSymbolAddress((void**)&yh,  g_yh);  cudaGetSymbolAddress((void**)&yl,  g_yl);
    cudaGetSymbolAddress((void**)&woh, g_woh);
    float* proj; cudaGetSymbolAddress((void**)&proj, g_proj);

    split2_kernel<<<(SEQ * HIDDEN / 4 + 255) / 256, 256>>>(x, xh, xl, SEQ * HIDDEN);
    split1_kernel<<<(PROJ_DIM * HIDDEN / 4 + 255) / 256, 256>>>(W_in, wih, PROJ_DIM * HIDDEN);
    split1_kernel<<<(HIDDEN * INTER / 4 + 255) / 256, 256>>>(W_out, woh, HIDDEN * INTER);

    gemm_mma_kernel<HIDDEN, PROJ_DIM, 256><<<dim3(33, 16), 512, SM256>>>(xh, xl, wih, proj, 0);
    gemm_mma_kernel<HIDDEN, PROJ_DIM, 64><<<dim3(1, 16), 512, SM64>>>(xh, xl, wih, proj, 8448);

    conv_silu_kernel<<<(SEQ * CONV_DIM + 255) / 256, 256>>>(conv_w, conv_b);
    dt_kernel<<<(SEQ * NH) / 256, 256>>>(dt_bias);
    acum_kernel<<<64, 256>>>(A_log);
    cb_kernel<<<dim3(4, 4, NCH), 256>>>();
    states_kernel<<<dim3(NH, NCH), 256>>>();
    carry_kernel<<<NH, 256>>>();
    y_kernel<<<dim3(4, NH, NCH), 256>>>(Dp);
    norm_kernel<<<SEQ, 256>>>(norm_w);

    gemm_mma_kernel<INTER, HIDDEN, 256><<<dim3(8, 16), 512, SM256>>>(yh, yl, woh, out, 0);
}

// round 15
// speedup vs baseline: 2.6813x; 1.2639x over previous
#include <cuda_runtime.h>
#include <cuda_fp16.h>
#include <stdint.h>
#include <math.h>

#define SEQ 2048
#define HIDDEN 2048
#define INTER 4096
#define NH 64
#define DH 64
#define DS 128
#define CHUNK 256
#define NCH 8
#define CONV_DIM 4352
#define PROJ_DIM 8512

// -------- scratch (device globals; no allocation allowed) --------
__device__ float g_proj[SEQ * PROJ_DIM];
__device__ float g_conv[SEQ * CONV_DIM];
__device__ float g_dt[SEQ * NH];
__device__ float g_acum[SEQ * NH];
__device__ float g_cb[NCH * CHUNK * CHUNK];
__device__ float g_states[NCH * NH * DH * DS];
__device__ float g_prev[NCH * NH * DH * DS];
__device__ float g_y[SEQ * INTER];

// fp16 operands for tensor-core GEMMs (single product: hi only)
__device__ __half g_xh[SEQ * HIDDEN];
__device__ __half g_wih[PROJ_DIM * HIDDEN];
__device__ __half g_yh[SEQ * INTER];
__device__ __half g_woh[HIDDEN * INTER];

// ======================= helpers =======================
__device__ __forceinline__ uint32_t smem_u32(const void* p) {
    uint32_t a;
    asm("{ .reg .u64 t; cvta.to.shared.u64 t, %1; cvt.u32.u64 %0, t; }" : "=r"(a) : "l"(p));
    return a;
}

#define LDSM4(r, a) \
    asm volatile("ldmatrix.sync.aligned.m8n8.x4.shared.b16 {%0,%1,%2,%3}, [%4];" \
        : "=r"((r)[0]), "=r"((r)[1]), "=r"((r)[2]), "=r"((r)[3]) : "r"(a))

#define MMA16816(c, a, b0, b1) \
    asm volatile("mma.sync.aligned.m16n8k16.row.col.f32.f16.f16.f32 " \
        "{%0,%1,%2,%3}, {%4,%5,%6,%7}, {%8,%9}, {%0,%1,%2,%3};" \
        : "+f"((c)[0]), "+f"((c)[1]), "+f"((c)[2]), "+f"((c)[3]) \
        : "r"((a)[0]), "r"((a)[1]), "r"((a)[2]), "r"((a)[3]), "r"(b0), "r"(b1))

__device__ __forceinline__ void cp16(uint32_t dst, const void* src) {
    unsigned long long g = (unsigned long long)__cvta_generic_to_global(src);
    asm volatile("cp.async.cg.shared.global [%0], [%1], 16;" :: "r"(dst), "l"(g));
}

// ======================= fp32 -> fp16 =======================
__global__ void split1_kernel(const float* __restrict__ in, __half* __restrict__ hi, int n) {
    int i = (blockIdx.x * blockDim.x + threadIdx.x) * 4;
    if (i >= n) return;
    float4 v = *(const float4*)(in + i);
    *(__half2*)(hi + i)     = __half2(__float2half_rn(v.x), __float2half_rn(v.y));
    *(__half2*)(hi + i + 2) = __half2(__float2half_rn(v.z), __float2half_rn(v.w));
}

// ======================= mma.sync GEMM: C[M, slice] = A[M,K] * B[N,K]^T =======================
// Single fp16 product (A hi x B hi). CTA 128 x NT (256 main / 64 tail),
// 512 threads (warps 4x4), 4-stage cp.async, smem pitch 40 half (80B).
#define PITCH 40

template<int K, int NT>
__device__ __forceinline__ void issue_tile(uint32_t st, int t, int bm, int bn,
        const __half* __restrict__ Ah, const __half* __restrict__ Bh, int tid) {
    constexpr int ABYTES = 128 * PITCH * 2;
    const int kt = t * 32;
    {   // A: 128 rows x 4 chunks = 512 chunks (one per thread)
        int r = tid >> 2, q = tid & 3;
        size_t src = (size_t)(bm + r) * K + kt + q * 8;
        cp16(st + (uint32_t)(r * PITCH + q * 8) * 2, Ah + src);
    }
    constexpr int BCH = NT * 4;
#pragma unroll
    for (int i = 0; i < (BCH + 511) / 512; i++) {
        int cid = tid + i * 512;
        if ((BCH % 512 == 0) || cid < BCH) {
            int r = cid >> 2, q = cid & 3;
            size_t src = (size_t)(bn + r) * K + kt + q * 8;
            cp16(st + ABYTES + (uint32_t)(r * PITCH + q * 8) * 2, Bh + src);
        }
    }
}

template<int K, int NS, int NT>
__global__ __launch_bounds__(512, 1) void gemm_mma_kernel(
        const __half* __restrict__ Ah, const __half* __restrict__ Bh,
        float* __restrict__ C, int n0) {
    extern __shared__ char smem[];
    constexpr int ABYTES = 128 * PITCH * 2;
    constexpr int BBYTES = NT * PITCH * 2;
    constexpr int STAGE = ABYTES + BBYTES;
    constexpr int T = K / 32;
    constexpr int WNF = NT / 32;        // n8 frags per warp (4 n-warps)
    constexpr int WSPAN = NT / 4;       // cols per warp

    const int tid = threadIdx.x;
    const int lane = tid & 31, wid = tid >> 5;
    const int wm = wid & 3, wn = wid >> 2;
    const int bm = blockIdx.y * 128;
    const int bn = n0 + blockIdx.x * NT;
    const uint32_t sb = smem_u32(smem);

    float acc[2][WNF][4];
#pragma unroll
    for (int i = 0; i < 2; i++)
#pragma unroll
        for (int j = 0; j < WNF; j++)
#pragma unroll
            for (int q = 0; q < 4; q++) acc[i][j][q] = 0.f;

    issue_tile<K, NT>(sb,             0, bm, bn, Ah, Bh, tid);
    asm volatile("cp.async.commit_group;" ::: "memory");
    issue_tile<K, NT>(sb + STAGE,     1, bm, bn, Ah, Bh, tid);
    asm volatile("cp.async.commit_group;" ::: "memory");
    issue_tile<K, NT>(sb + 2 * STAGE, 2, bm, bn, Ah, Bh, tid);
    asm volatile("cp.async.commit_group;" ::: "memory");

    const int lrow = lane & 15;
    const int lcol = (lane >> 4) * 8;
    const uint32_t aoff = (uint32_t)((wm * 32 + lrow) * PITCH + lcol) * 2;
    const uint32_t boff = ABYTES + (uint32_t)((wn * WSPAN + lrow) * PITCH + lcol) * 2;

    for (int t = 0; t < T; t++) {
        asm volatile("cp.async.wait_group 2;" ::: "memory");
        __syncthreads();
        const uint32_t stg = sb + (uint32_t)(t & 3) * STAGE;
#pragma unroll
        for (int kk = 0; kk < 32; kk += 16) {
            uint32_t ah[2][4];
#pragma unroll
            for (int fm = 0; fm < 2; fm++)
                LDSM4(ah[fm], stg + aoff + (uint32_t)(fm * 16 * PITCH + kk) * 2);
#pragma unroll
            for (int g = 0; g < WNF / 2; g++) {
                uint32_t bd = stg + boff + (uint32_t)(g * 16 * PITCH + kk) * 2;
                uint32_t rh[4];
                LDSM4(rh, bd);
#pragma unroll
                for (int fm = 0; fm < 2; fm++) {
                    MMA16816(acc[fm][2 * g],     ah[fm], rh[0], rh[2]);
                    MMA16816(acc[fm][2 * g + 1], ah[fm], rh[1], rh[3]);
                }
            }
        }
        if (t + 3 < T)
            issue_tile<K, NT>(sb + (uint32_t)((t + 3) & 3) * STAGE, t + 3, bm, bn, Ah, Bh, tid);
        asm volatile("cp.async.commit_group;" ::: "memory");
    }

    const int crow = lane >> 2, ccol = (lane & 3) * 2;
#pragma unroll
    for (int fm = 0; fm < 2; fm++)
#pragma unroll
        for (int fn = 0; fn < WNF; fn++) {
            int m = bm + wm * 32 + fm * 16 + crow;
            int n = bn + wn * WSPAN + fn * 8 + ccol;
            *(float2*)&C[(size_t)m * NS + n]       = make_float2(acc[fm][fn][0], acc[fm][fn][1]);
            *(float2*)&C[(size_t)(m + 8) * NS + n] = make_float2(acc[fm][fn][2], acc[fm][fn][3]);
        }
}

// ======================= depthwise causal conv (K=4) + SiLU =======================
__global__ void conv_silu_kernel(const float* __restrict__ conv_w,
                                 const float* __restrict__ conv_b) {
    int idx = blockIdx.x * blockDim.x + threadIdx.x;
    if (idx >= SEQ * CONV_DIM) return;
    int s = idx / CONV_DIM;
    int c = idx - s * CONV_DIM;
    float w0 = conv_w[c * 4 + 0], w1 = conv_w[c * 4 + 1];
    float w2 = conv_w[c * 4 + 2], w3 = conv_w[c * 4 + 3];
    const float* col = g_proj + INTER + c;
    float acc = conv_b[c];
    if (s >= 3) acc = fmaf(col[(size_t)(s - 3) * PROJ_DIM], w0, acc);
    if (s >= 2) acc = fmaf(col[(size_t)(s - 2) * PROJ_DIM], w1, acc);
    if (s >= 1) acc = fmaf(col[(size_t)(s - 1) * PROJ_DIM], w2, acc);
    acc = fmaf(col[(size_t)s * PROJ_DIM], w3, acc);
    float sig = 1.f / (1.f + __expf(-acc));
    g_conv[idx] = acc * sig;
}

// ======================= dt = softplus(dt_raw + dt_bias) =======================
__global__ void dt_kernel(const float* __restrict__ dt_bias) {
    int idx = blockIdx.x * blockDim.x + threadIdx.x;
    int h = idx & 63;
    int s = idx >> 6;
    float v = g_proj[(size_t)s * PROJ_DIM + (INTER + CONV_DIM) + h] + dt_bias[h];
    g_dt[idx] = (v > 20.f) ? v : log1pf(__expf(v));
}

// ======================= per-chunk cumsum(dt*A): warp scan per (c,h) =======================
__global__ void acum_kernel(const float* __restrict__ A_log) {
    int wg = blockIdx.x * 8 + (threadIdx.x >> 5);
    int lane = threadIdx.x & 31;
    int c = wg >> 6, h = wg & 63;
    float A = -__expf(A_log[h]);
    const float* dtp = g_dt + ((size_t)c * CHUNK) * NH + h;
    float v[8];
    float run = 0.f;
#pragma unroll
    for (int j = 0; j < 8; j++) {
        v[j] = dtp[(size_t)(lane * 8 + j) * NH] * A;
        run += v[j];
    }
    float s = run;
#pragma unroll
    for (int o = 1; o < 32; o <<= 1) {
        float t = __shfl_up_sync(0xffffffffu, s, o);
        if (lane >= o) s += t;
    }
    float acc = s - run;
    float* acp = g_acum + ((size_t)c * CHUNK) * NH + h;
#pragma unroll
    for (int j = 0; j < 8; j++) {
        acc += v[j];
        acp[(size_t)(lane * 8 + j) * NH] = acc;
    }
}

// ======================= CB[c][t][s] = C_t . B_s (shared over heads), s<=t tiles only =======================
__global__ __launch_bounds__(256) void cb_kernel() {
    int st = blockIdx.x, tt = blockIdx.y, c = blockIdx.z;
    if (st > tt) return;
    __shared__ float Cs[32][68];
    __shared__ float Bs2[32][68];
    const int tid = threadIdx.x;
    const int tx = tid & 15, ty = tid >> 4;
    float acc[4][4] = {};
    for (int n0 = 0; n0 < DS; n0 += 32) {
        __syncthreads();
        for (int e = tid; e < 64 * 32; e += 256) {
            int r = e >> 5, kk = e & 31;
            Cs[kk][r]  = g_conv[(size_t)(c * CHUNK + tt * 64 + r) * CONV_DIM + INTER + DS + n0 + kk];
            Bs2[kk][r] = g_conv[(size_t)(c * CHUNK + st * 64 + r) * CONV_DIM + INTER + n0 + kk];
        }
        __syncthreads();
#pragma unroll
        for (int k = 0; k < 32; k++) {
            float4 a = *(const float4*)&Cs[k][ty * 4];
            float4 b = *(const float4*)&Bs2[k][tx * 4];
            float av[4] = {a.x, a.y, a.z, a.w};
            float bv[4] = {b.x, b.y, b.z, b.w};
#pragma unroll
            for (int i = 0; i < 4; i++)
#pragma unroll
                for (int j = 0; j < 4; j++)
                    acc[i][j] = fmaf(av[i], bv[j], acc[i][j]);
        }
    }
#pragma unroll
    for (int i = 0; i < 4; i++)
        *(float4*)&g_cb[(size_t)c * CHUNK * CHUNK + (size_t)(tt * 64 + ty * 4 + i) * CHUNK + st * 64 + tx * 4] =
            make_float4(acc[i][0], acc[i][1], acc[i][2], acc[i][3]);
}

// ======================= chunk end states: states[c][h][p][n] =======================
__global__ __launch_bounds__(256) void states_kernel() {
    int h = blockIdx.x, c = blockIdx.y;
    __shared__ float Bt[32][DS];
    __shared__ float Xt[32][DH];
    __shared__ float wv[32];
    const int tid = threadIdx.x;
    const int p = tid >> 2, ng = tid & 3;
    float acc[32];
#pragma unroll
    for (int j = 0; j < 32; j++) acc[j] = 0.f;
    float Aend = g_acum[(size_t)(c * CHUNK + CHUNK - 1) * NH + h];
    for (int lt = 0; lt < 8; lt++) {
        __syncthreads();
        for (int e = tid; e < 32 * DS; e += 256) {
            int r = e >> 7, n = e & 127;
            Bt[r][n] = g_conv[(size_t)(c * CHUNK + lt * 32 + r) * CONV_DIM + INTER + n];
        }
        for (int e = tid; e < 32 * DH; e += 256) {
            int r = e >> 6, pp = e & 63;
            Xt[r][pp] = g_conv[(size_t)(c * CHUNK + lt * 32 + r) * CONV_DIM + h * DH + pp];
        }
        if (tid < 32) {
            int l = lt * 32 + tid;
            float ac = g_acum[(size_t)(c * CHUNK + l) * NH + h];
            wv[tid] = __expf(Aend - ac) * g_dt[(size_t)(c * CHUNK + l) * NH + h];
        }
        __syncthreads();
#pragma unroll 4
        for (int ls = 0; ls < 32; ls++) {
            float xv = Xt[ls][p] * wv[ls];
            const float* br = &Bt[ls][ng * 32];
#pragma unroll
            for (int j = 0; j < 32; j += 4) {
                float4 b4 = *(const float4*)(br + j);
                acc[j + 0] = fmaf(xv, b4.x, acc[j + 0]);
                acc[j + 1] = fmaf(xv, b4.y, acc[j + 1]);
                acc[j + 2] = fmaf(xv, b4.z, acc[j + 2]);
                acc[j + 3] = fmaf(xv, b4.w, acc[j + 3]);
            }
        }
    }
    float* dst = &g_states[(((size_t)c * NH + h) * DH + p) * DS + ng * 32];
#pragma unroll
    for (int j = 0; j < 32; j += 4)
        *(float4*)(dst + j) = make_float4(acc[j], acc[j + 1], acc[j + 2], acc[j + 3]);
}

// ======================= inter-chunk carry scan =======================
__global__ void carry_kernel() {
    int h = blockIdx.x;
    int tid = threadIdx.x;
    float carry[32];
#pragma unroll
    for (int j = 0; j < 32; j++) carry[j] = 0.f;
    for (int c = 0; c < NCH; c++) {
        float dec = __expf(g_acum[(size_t)(c * CHUNK + CHUNK - 1) * NH + h]);
        size_t off = ((size_t)c * NH + h) * DH * DS + (size_t)tid * 32;
#pragma unroll
        for (int j = 0; j < 32; j += 4) {
            float4 st = *(const float4*)&g_states[off + j];
            *(float4*)&g_prev[off + j] = make_float4(carry[j], carry[j + 1], carry[j + 2], carry[j + 3]);
            carry[j + 0] = fmaf(carry[j + 0], dec, st.x);
            carry[j + 1] = fmaf(carry[j + 1], dec, st.y);
            carry[j + 2] = fmaf(carry[j + 2], dec, st.z);
            carry[j + 3] = fmaf(carry[j + 3], dec, st.w);
        }
    }
}

// ======================= Y = intra + inter + D skip =======================
__global__ __launch_bounds__(256) void y_kernel(const float* __restrict__ Dp) {
    const int tt = blockIdx.x;
    const int h  = blockIdx.y;
    const int c  = blockIdx.z;
    __shared__ float sM[64][68];
    __shared__ float sX[64][68];
    __shared__ float sAcT[64], sAcS[64], sDt[64], sEt[64], sEs[64];
    const int tid = threadIdx.x;
    const int tx = tid & 15, ty = tid >> 4;

    if (tid < 64)
        sAcT[tid] = g_acum[(size_t)(c * CHUNK + tt * 64 + tid) * NH + h];

    float acc[4][4] = {};

    for (int n0 = 0; n0 < DS; n0 += 32) {
        __syncthreads();
        for (int e = tid; e < 64 * 32; e += 256) {
            int r = e >> 5, kk = e & 31;
            sM[kk][r] = g_conv[(size_t)(c * CHUNK + tt * 64 + r) * CONV_DIM + INTER + DS + n0 + kk];
            sX[kk][r] = g_prev[(((size_t)c * NH + h) * DH + r) * DS + n0 + kk];
        }
        __syncthreads();
#pragma unroll
        for (int k = 0; k < 32; k++) {
            float4 a = *(const float4*)&sM[k][ty * 4];
            float4 b = *(const float4*)&sX[k][tx * 4];
            float av[4] = {a.x, a.y, a.z, a.w};
            float bv[4] = {b.x, b.y, b.z, b.w};
#pragma unroll
            for (int i = 0; i < 4; i++)
#pragma unroll
                for (int j = 0; j < 4; j++)
                    acc[i][j] = fmaf(av[i], bv[j], acc[i][j]);
        }
    }
#pragma unroll
    for (int i = 0; i < 4; i++) {
        float e = __expf(sAcT[ty * 4 + i]);
#pragma unroll
        for (int j = 0; j < 4; j++) acc[i][j] *= e;
    }

    for (int st = 0; st <= tt; st++) {
        __syncthreads();
        if (tid < 64) {
            sAcS[tid] = g_acum[(size_t)(c * CHUNK + st * 64 + tid) * NH + h];
            sDt[tid]  = g_dt  [(size_t)(c * CHUNK + st * 64 + tid) * NH + h];
        }
        __syncthreads();
        if (st < tt && tid < 64) {
            float ref = sAcS[63];
            sEt[tid] = __expf(sAcT[tid] - ref);
            sEs[tid] = __expf(ref - sAcS[tid]) * sDt[tid];
        }
        __syncthreads();
        for (int e = tid; e < 64 * 64; e += 256) {
            int t = e >> 6, s = e & 63;
            float cb = g_cb[(size_t)c * CHUNK * CHUNK + (size_t)(tt * 64 + t) * CHUNK + st * 64 + s];
            float m;
            if (st < tt) m = cb * sEt[t] * sEs[s];
            else         m = (s <= t) ? cb * __expf(sAcT[t] - sAcS[s]) * sDt[s] : 0.f;
            sM[s][t] = m;
        }
        for (int e = tid; e < 64 * 64; e += 256) {
            int s = e >> 6, pp = e & 63;
            sX[s][pp] = g_conv[(size_t)(c * CHUNK + st * 64 + s) * CONV_DIM + h * DH + pp];
        }
        __syncthreads();
#pragma unroll 8
        for (int s = 0; s < 64; s++) {
            float4 a = *(const float4*)&sM[s][ty * 4];
            float4 b = *(const float4*)&sX[s][tx * 4];
            float av[4] = {a.x, a.y, a.z, a.w};
            float bv[4] = {b.x, b.y, b.z, b.w};
#pragma unroll
            for (int i = 0; i < 4; i++)
#pragma unroll
                for (int j = 0; j < 4; j++)
                    acc[i][j] = fmaf(av[i], bv[j], acc[i][j]);
        }
    }

    float dv = Dp[h];
#pragma unroll
    for (int i = 0; i < 4; i++)
#pragma unroll
        for (int j = 0; j < 4; j++)
            acc[i][j] = fmaf(dv, sX[ty * 4 + i][tx * 4 + j], acc[i][j]);

#pragma unroll
    for (int i = 0; i < 4; i++)
        *(float4*)&g_y[(size_t)(c * CHUNK + tt * 64 + ty * 4 + i) * INTER + h * DH + tx * 4] =
            make_float4(acc[i][0], acc[i][1], acc[i][2], acc[i][3]);
}

// ======================= gated RMSNorm -> fp16 output =======================
__global__ __launch_bounds__(256) void norm_kernel(const float* __restrict__ norm_w) {
    int s = blockIdx.x;
    int tid = threadIdx.x;
    float v[16];
    float ss = 0.f;
#pragma unroll
    for (int q = 0; q < 4; q++) {
        int i4 = tid + q * 256;
        float4 y4 = *(const float4*)&g_y[(size_t)s * INTER + (size_t)i4 * 4];
        float4 g4 = *(const float4*)&g_proj[(size_t)s * PROJ_DIM + (size_t)i4 * 4];
        float t0 = y4.x * (g4.x / (1.f + __expf(-g4.x)));
        float t1 = y4.y * (g4.y / (1.f + __expf(-g4.y)));
        float t2 = y4.z * (g4.z / (1.f + __expf(-g4.z)));
        float t3 = y4.w * (g4.w / (1.f + __expf(-g4.w)));
        v[q * 4 + 0] = t0; v[q * 4 + 1] = t1; v[q * 4 + 2] = t2; v[q * 4 + 3] = t3;
        ss += t0 * t0 + t1 * t1 + t2 * t2 + t3 * t3;
    }
#pragma unroll
    for (int o = 16; o > 0; o >>= 1) ss += __shfl_xor_sync(0xffffffffu, ss, o);
    __shared__ float red[8];
    if ((tid & 31) == 0) red[tid >> 5] = ss;
    __syncthreads();
    float tot = red[0] + red[1] + red[2] + red[3] + red[4] + red[5] + red[6] + red[7];
    float scale = rsqrtf(tot * (1.f / INTER) + 1e-5f);
#pragma unroll
    for (int q = 0; q < 4; q++) {
        int i4 = tid + q * 256;
        float4 w4 = *(const float4*)&norm_w[(size_t)i4 * 4];
        float o0 = v[q * 4 + 0] * scale * w4.x;
        float o1 = v[q * 4 + 1] * scale * w4.y;
        float o2 = v[q * 4 + 2] * scale * w4.z;
        float o3 = v[q * 4 + 3] * scale * w4.w;
        size_t base = (size_t)s * INTER + (size_t)i4 * 4;
        *(__half2*)(g_yh + base)     = __half2(__float2half_rn(o0), __float2half_rn(o1));
        *(__half2*)(g_yh + base + 2) = __half2(__float2half_rn(o2), __float2half_rn(o3));
    }
}

// ======================= launch =======================
extern "C" void kernel_launch(void* const* d_in, const int* in_sizes, int n_in,
                              void* d_out, int out_size) {
    (void)in_sizes; (void)n_in; (void)out_size;
    const float* x       = (const float*)d_in[0];
    const float* W_in    = (const float*)d_in[1];
    const float* conv_w  = (const float*)d_in[2];
    const float* conv_b  = (const float*)d_in[3];
    const float* dt_bias = (const float*)d_in[4];
    const float* A_log   = (const float*)d_in[5];
    const float* Dp      = (const float*)d_in[6];
    const float* norm_w  = (const float*)d_in[7];
    const float* W_out   = (const float*)d_in[8];
    float* out = (float*)d_out;

    // stage = A(10240) + B(NT*80): NT=256 -> 30720; NT=64 -> 15360. 4 stages.
    const int SM256 = 4 * (128 * PITCH * 2 + 256 * PITCH * 2); // 122880
    const int SM64  = 4 * (128 * PITCH * 2 + 64 * PITCH * 2);  // 61440
    cudaFuncSetAttribute(gemm_mma_kernel<HIDDEN, PROJ_DIM, 256>,
                         cudaFuncAttributeMaxDynamicSharedMemorySize, SM256);
    cudaFuncSetAttribute(gemm_mma_kernel<HIDDEN, PROJ_DIM, 64>,
                         cudaFuncAttributeMaxDynamicSharedMemorySize, SM64);
    cudaFuncSetAttribute(gemm_mma_kernel<INTER, HIDDEN, 256>,
                         cudaFuncAttributeMaxDynamicSharedMemorySize, SM256);

    __half *xh, *wih, *yh, *woh;
    cudaGetSymbolAddress((void**)&xh,  g_xh);
    cudaGetSymbolAddress((void**)&wih, g_wih);
    cudaGetSymbolAddress((void**)&yh,  g_yh);
    cudaGetSymbolAddress((void**)&woh, g_woh);
    float* proj; cudaGetSymbolAddress((void**)&proj, g_proj);

    split1_kernel<<<(SEQ * HIDDEN / 4 + 255) / 256, 256>>>(x, xh, SEQ * HIDDEN);
    split1_kernel<<<(PROJ_DIM * HIDDEN / 4 + 255) / 256, 256>>>(W_in, wih, PROJ_DIM * HIDDEN);
    split1_kernel<<<(HIDDEN * INTER / 4 + 255) / 256, 256>>>(W_out, woh, HIDDEN * INTER);

    gemm_mma_kernel<HIDDEN, PROJ_DIM, 256><<<dim3(33, 16), 512, SM256>>>(xh, wih, proj, 0);
    gemm_mma_kernel<HIDDEN, PROJ_DIM, 64><<<dim3(1, 16), 512, SM64>>>(xh, wih, proj, 8448);

    conv_silu_kernel<<<(SEQ * CONV_DIM + 255) / 256, 256>>>(conv_w, conv_b);
    dt_kernel<<<(SEQ * NH) / 256, 256>>>(dt_bias);
    acum_kernel<<<64, 256>>>(A_log);
    cb_kernel<<<dim3(4, 4, NCH), 256>>>();
    states_kernel<<<dim3(NH, NCH), 256>>>();
    carry_kernel<<<NH, 256>>>();
    y_kernel<<<dim3(4, NH, NCH), 256>>>(Dp);
    norm_kernel<<<SEQ, 256>>>(norm_w);

    gemm_mma_kernel<INTER, HIDDEN, 256><<<dim3(8, 16), 512, SM256>>>(yh, woh, out, 0);
}